// round 3
// baseline (speedup 1.0000x reference)
#include <cuda_runtime.h>

// Problem constants (fixed shapes per reference)
#define Nn   100000
#define Ee   1600000
#define FIN  256
#define HID  128
#define NG   512
#define NB_SCAN 98        // ceil(100000/1024)

// ---------------- scratch (static device memory; no allocs allowed) ----------
__device__ float g_H[(size_t)Nn * 256];     // GEMM output [N, 256] (init|root)
__device__ float g_h[(size_t)Nn * 128];     // conv0 output
__device__ float g_deg[Nn];                 // degree -> dinv (in place)
__device__ float g_norm[Ee];                // per-edge norm (unsorted)
__device__ int   g_cnt[Nn];                 // in-degree counts
__device__ int   g_off[Nn];                 // CSR offsets (exclusive)
__device__ int   g_cur[Nn];                 // scatter cursors
__device__ int   g_src[Ee];                 // CSR: source node per edge (sorted by dst)
__device__ float g_nrm_s[Ee];               // CSR: norm per edge (sorted by dst)
__device__ int   g_psum[NB_SCAN];           // scan partials
__device__ int   g_boff[NB_SCAN];           // scan block offsets
__device__ float g_wcat[256 * 256];         // concatenated weights [K, 256]
__device__ float g_pool[NG * HID];          // pooled sums
__device__ float g_pcnt[NG];                // pooled counts

// ---------------- small utility kernels --------------------------------------
__global__ void k_zero_node(void) {
    int i = blockIdx.x * blockDim.x + threadIdx.x;
    if (i < Nn) { g_deg[i] = 0.f; g_cnt[i] = 0; }
}
__global__ void k_zero_pool(void) {
    int i = blockIdx.x * blockDim.x + threadIdx.x;
    if (i < NG * HID) g_pool[i] = 0.f;
    if (i < NG) g_pcnt[i] = 0.f;
}
__global__ void k_deg(const int* __restrict__ ei, const float* __restrict__ w) {
    int e = blockIdx.x * blockDim.x + threadIdx.x;
    if (e >= Ee) return;
    int col = ei[Ee + e];
    atomicAdd(&g_deg[col], w[e]);
}
__global__ void k_dinv(void) {
    int i = blockIdx.x * blockDim.x + threadIdx.x;
    if (i >= Nn) return;
    float d = g_deg[i];
    g_deg[i] = (d > 0.f) ? rsqrtf(d) : 0.f;
}
__global__ void k_norm_cnt(const int* __restrict__ ei, const float* __restrict__ w) {
    int e = blockIdx.x * blockDim.x + threadIdx.x;
    if (e >= Ee) return;
    int row = ei[e];
    int col = ei[Ee + e];
    g_norm[e] = g_deg[row] * w[e] * g_deg[col];
    atomicAdd(&g_cnt[col], 1);
}
// ---- 3-phase exclusive scan of g_cnt over Nn --------------------------------
__global__ void k_scan1(void) {
    __shared__ int s[1024];
    int t = threadIdx.x;
    int i = blockIdx.x * 1024 + t;
    s[t] = (i < Nn) ? g_cnt[i] : 0;
    __syncthreads();
    for (int d = 512; d > 0; d >>= 1) {
        if (t < d) s[t] += s[t + d];
        __syncthreads();
    }
    if (t == 0) g_psum[blockIdx.x] = s[0];
}
__global__ void k_scan2(void) {
    int run = 0;
    for (int b = 0; b < NB_SCAN; b++) { g_boff[b] = run; run += g_psum[b]; }
}
__global__ void k_scan3(void) {
    __shared__ int s[1024];
    int t = threadIdx.x;
    int i = blockIdx.x * 1024 + t;
    int v = (i < Nn) ? g_cnt[i] : 0;
    s[t] = v;
    __syncthreads();
    for (int d = 1; d < 1024; d <<= 1) {
        int add = (t >= d) ? s[t - d] : 0;
        __syncthreads();
        s[t] += add;
        __syncthreads();
    }
    if (i < Nn) {
        int excl = g_boff[blockIdx.x] + s[t] - v;
        g_off[i] = excl;
        g_cur[i] = excl;
    }
}
__global__ void k_scatter(const int* __restrict__ ei) {
    int e = blockIdx.x * blockDim.x + threadIdx.x;
    if (e >= Ee) return;
    int row = ei[e];
    int col = ei[Ee + e];
    int pos = atomicAdd(&g_cur[col], 1);
    g_src[pos] = row;
    g_nrm_s[pos] = g_norm[e];
}
__global__ void k_wcat(const float* __restrict__ wi, const float* __restrict__ wr, int K) {
    int idx = blockIdx.x * blockDim.x + threadIdx.x;
    if (idx >= K * 256) return;
    int k = idx >> 8, c = idx & 255;
    g_wcat[idx] = (c < HID) ? wi[k * HID + c] : wr[k * HID + (c - HID)];
}

// ---------------- GEMM: g_H[M,256] = A[M,K] @ g_wcat[K,256] ------------------
// A is either the external x pointer (EXTERNAL=true) or internal g_h (false).
#define BM 64
#define BN 64
#define BK 16
template <bool EXTERNAL>
__global__ void k_gemm(const float* __restrict__ Aext, int M, int K) {
    __shared__ float As[BK][BM + 1];
    __shared__ float Bs[BK][BN];
    const float* __restrict__ A = EXTERNAL ? Aext : (const float*)g_h;
    int tx = threadIdx.x & 15;        // 0..15
    int ty = threadIdx.x >> 4;        // 0..15
    int rowBase = blockIdx.x * BM;
    int colBase = blockIdx.y * BN;
    float acc[4][4] = {};
    for (int k0 = 0; k0 < K; k0 += BK) {
        #pragma unroll
        for (int i = threadIdx.x; i < BM * BK; i += 256) {
            int m = i / BK, kk = i % BK;
            int gm = rowBase + m;
            As[kk][m] = (gm < M) ? A[(long)gm * K + k0 + kk] : 0.f;
        }
        #pragma unroll
        for (int i = threadIdx.x; i < BK * BN; i += 256) {
            int kk = i / BN, c = i % BN;
            Bs[kk][c] = g_wcat[(k0 + kk) * 256 + colBase + c];
        }
        __syncthreads();
        #pragma unroll
        for (int kk = 0; kk < BK; kk++) {
            float a[4], b[4];
            #pragma unroll
            for (int i = 0; i < 4; i++) a[i] = As[kk][ty * 4 + i];
            #pragma unroll
            for (int j = 0; j < 4; j++) b[j] = Bs[kk][tx * 4 + j];
            #pragma unroll
            for (int i = 0; i < 4; i++)
                #pragma unroll
                for (int j = 0; j < 4; j++) acc[i][j] += a[i] * b[j];
        }
        __syncthreads();
    }
    #pragma unroll
    for (int i = 0; i < 4; i++) {
        int gm = rowBase + ty * 4 + i;
        if (gm < M) {
            #pragma unroll
            for (int j = 0; j < 4; j++)
                g_H[(size_t)gm * 256 + colBase + tx * 4 + j] = acc[i][j];
        }
    }
}

// ---------------- Aggregation: warp per node ---------------------------------
// out0[n] = relu( sum_e norm_e * Hinit[src_e] + Hroot[n] + b )
__global__ void k_agg0(const float* __restrict__ bias) {
    int warp = threadIdx.x >> 5;
    int lane = threadIdx.x & 31;
    int n = blockIdx.x * 8 + warp;
    if (n >= Nn) return;
    int start = g_off[n];
    int cnt = g_cnt[n];
    float4 acc = make_float4(0.f, 0.f, 0.f, 0.f);
    for (int e = start; e < start + cnt; e++) {
        int s = g_src[e];
        float nm = g_nrm_s[e];
        float4 v = *(const float4*)&g_H[(size_t)s * 256 + lane * 4];
        acc.x += nm * v.x; acc.y += nm * v.y; acc.z += nm * v.z; acc.w += nm * v.w;
    }
    float4 r = *(const float4*)&g_H[(size_t)n * 256 + 128 + lane * 4];
    float4 b = *(const float4*)&bias[lane * 4];
    float4 o;
    o.x = fmaxf(acc.x + r.x + b.x, 0.f);
    o.y = fmaxf(acc.y + r.y + b.y, 0.f);
    o.z = fmaxf(acc.z + r.z + b.z, 0.f);
    o.w = fmaxf(acc.w + r.w + b.w, 0.f);
    *(float4*)&g_h[(size_t)n * 128 + lane * 4] = o;
}

// conv1 aggregation fused with mean-pool accumulation
__global__ void k_agg1(const float* __restrict__ bias, const int* __restrict__ batch) {
    int warp = threadIdx.x >> 5;
    int lane = threadIdx.x & 31;
    int n = blockIdx.x * 8 + warp;
    if (n >= Nn) return;
    int start = g_off[n];
    int cnt = g_cnt[n];
    float4 acc = make_float4(0.f, 0.f, 0.f, 0.f);
    for (int e = start; e < start + cnt; e++) {
        int s = g_src[e];
        float nm = g_nrm_s[e];
        float4 v = *(const float4*)&g_H[(size_t)s * 256 + lane * 4];
        acc.x += nm * v.x; acc.y += nm * v.y; acc.z += nm * v.z; acc.w += nm * v.w;
    }
    float4 r = *(const float4*)&g_H[(size_t)n * 256 + 128 + lane * 4];
    float4 b = *(const float4*)&bias[lane * 4];
    float4 o;
    o.x = fmaxf(acc.x + r.x + b.x, 0.f);
    o.y = fmaxf(acc.y + r.y + b.y, 0.f);
    o.z = fmaxf(acc.z + r.z + b.z, 0.f);
    o.w = fmaxf(acc.w + r.w + b.w, 0.f);
    int g = batch[n];
    float* p = &g_pool[(size_t)g * 128 + lane * 4];
    atomicAdd(p + 0, o.x);
    atomicAdd(p + 1, o.y);
    atomicAdd(p + 2, o.z);
    atomicAdd(p + 3, o.w);
    if (lane == 0) atomicAdd(&g_pcnt[g], 1.f);
}

// ---------------- pool finalize + MLP ----------------------------------------
__global__ void k_mlp(const float* __restrict__ w1, const float* __restrict__ b1,
                      const float* __restrict__ w2, const float* __restrict__ b2,
                      float* __restrict__ out) {
    __shared__ float gx[128];
    __shared__ float hid[256];
    int g = blockIdx.x;
    int t = threadIdx.x;
    if (t < 128) {
        float c = fmaxf(g_pcnt[g], 1.f);
        gx[t] = g_pool[(size_t)g * 128 + t] / c;
    }
    __syncthreads();
    float acc = b1[t];
    #pragma unroll 8
    for (int k = 0; k < 128; k++) acc += gx[k] * w1[k * 256 + t];
    hid[t] = fmaxf(acc, 0.f);
    __syncthreads();
    int warp = t >> 5, lane = t & 31;
    if (warp < 2) {
        int c = warp;  // class index
        float s = 0.f;
        for (int k = lane; k < 256; k += 32) s += hid[k] * w2[k * 2 + c];
        #pragma unroll
        for (int d = 16; d > 0; d >>= 1) s += __shfl_xor_sync(0xFFFFFFFF, s, d);
        if (lane == 0) out[g * 2 + c] = s + b2[c];
    }
}

// ---------------- launch -----------------------------------------------------
extern "C" void kernel_launch(void* const* d_in, const int* in_sizes, int n_in,
                              void* d_out, int out_size) {
    const float* x     = (const float*)d_in[0];
    const int*   ei    = (const int*)d_in[1];
    const float* ea    = (const float*)d_in[2];
    const int*   batch = (const int*)d_in[3];
    const float* w_init0 = (const float*)d_in[4];
    const float* w_root0 = (const float*)d_in[5];
    const float* b0      = (const float*)d_in[6];
    const float* w_init1 = (const float*)d_in[7];
    const float* w_root1 = (const float*)d_in[8];
    const float* b1      = (const float*)d_in[9];
    const float* mlp_w1  = (const float*)d_in[10];
    const float* mlp_b1  = (const float*)d_in[11];
    const float* mlp_w2  = (const float*)d_in[12];
    const float* mlp_b2  = (const float*)d_in[13];
    float* out = (float*)d_out;

    const int TB = 256;
    int nBlkN = (Nn + TB - 1) / TB;
    int nBlkE = (Ee + TB - 1) / TB;

    // norm + CSR build (reused by both convs)
    k_zero_node<<<nBlkN, TB>>>();
    k_zero_pool<<<(NG * HID + TB - 1) / TB, TB>>>();
    k_deg<<<nBlkE, TB>>>(ei, ea);
    k_dinv<<<nBlkN, TB>>>();
    k_norm_cnt<<<nBlkE, TB>>>(ei, ea);
    k_scan1<<<NB_SCAN, 1024>>>();
    k_scan2<<<1, 1>>>();
    k_scan3<<<NB_SCAN, 1024>>>();
    k_scatter<<<nBlkE, TB>>>(ei);

    // conv0
    k_wcat<<<(256 * 256 + TB - 1) / TB, TB>>>(w_init0, w_root0, 256);
    {
        dim3 grid((Nn + BM - 1) / BM, 256 / BN);
        k_gemm<true><<<grid, 256>>>(x, Nn, 256);
    }
    k_agg0<<<(Nn + 7) / 8, 256>>>(b0);

    // conv1
    k_wcat<<<(128 * 256 + TB - 1) / TB, TB>>>(w_init1, w_root1, 128);
    {
        dim3 grid((Nn + BM - 1) / BM, 256 / BN);
        k_gemm<false><<<grid, 256>>>(nullptr, Nn, 128);
    }
    k_agg1<<<(Nn + 7) / 8, 256>>>(b1, batch);

    // pool + MLP
    k_mlp<<<NG, 256>>>(mlp_w1, mlp_b1, mlp_w2, mlp_b2, out);
}

// round 5
// speedup vs baseline: 1.7675x; 1.7675x over previous
#include <cuda_runtime.h>
#include <cuda_bf16.h>
#include <cstdint>

// Problem constants
#define Nn   100000
#define Ee   1600000
#define HID  128
#define NG   512
#define NB_SCAN 98        // ceil(100000/1024)

// ---------------- scratch (static device memory) -----------------------------
__device__ __align__(128) float g_Hi[(size_t)Nn * 128];   // GEMM init-half out
__device__ __align__(128) float g_Hr[(size_t)Nn * 128];   // GEMM root-half out
__device__ __align__(128) __nv_bfloat16 g_Ah0[(size_t)Nn * 256];
__device__ __align__(128) __nv_bfloat16 g_Al0[(size_t)Nn * 256];
__device__ __align__(128) __nv_bfloat16 g_Ah1[(size_t)Nn * 128];
__device__ __align__(128) __nv_bfloat16 g_Al1[(size_t)Nn * 128];
__device__ __align__(128) __nv_bfloat16 g_Bh0[256 * 256];
__device__ __align__(128) __nv_bfloat16 g_Bl0[256 * 256];
__device__ __align__(128) __nv_bfloat16 g_Bh1[256 * 128];
__device__ __align__(128) __nv_bfloat16 g_Bl1[256 * 128];
__device__ float g_deg[Nn];
__device__ float g_norm[Ee];
__device__ int   g_cnt[Nn];
__device__ int   g_off[Nn];
__device__ int   g_cur[Nn];
__device__ int   g_src[Ee];
__device__ float g_nrm_s[Ee];
__device__ int   g_psum[NB_SCAN];
__device__ int   g_boff[NB_SCAN];
__device__ float g_pool[NG * HID];
__device__ float g_pcnt[NG];

// ---------------- PTX helpers (base sm_100 features only) --------------------
__device__ __forceinline__ uint32_t s2u(const void* p) {
    uint32_t a;
    asm("{ .reg .u64 t; cvta.to.shared.u64 t, %1; cvt.u32.u64 %0, t; }" : "=r"(a) : "l"(p));
    return a;
}
__device__ __forceinline__ void ldm_x4(uint32_t& r0, uint32_t& r1, uint32_t& r2, uint32_t& r3,
                                       uint32_t addr) {
    asm volatile("ldmatrix.sync.aligned.m8n8.x4.shared.b16 {%0,%1,%2,%3}, [%4];"
                 : "=r"(r0), "=r"(r1), "=r"(r2), "=r"(r3) : "r"(addr));
}
__device__ __forceinline__ void ldm_x2(uint32_t& r0, uint32_t& r1, uint32_t addr) {
    asm volatile("ldmatrix.sync.aligned.m8n8.x2.shared.b16 {%0,%1}, [%2];"
                 : "=r"(r0), "=r"(r1) : "r"(addr));
}
__device__ __forceinline__ void mma_bf16(float* c, const uint32_t* a, const uint32_t* b) {
    asm volatile(
        "mma.sync.aligned.m16n8k16.row.col.f32.bf16.bf16.f32 "
        "{%0,%1,%2,%3}, {%4,%5,%6,%7}, {%8,%9}, {%0,%1,%2,%3};"
        : "+f"(c[0]), "+f"(c[1]), "+f"(c[2]), "+f"(c[3])
        : "r"(a[0]), "r"(a[1]), "r"(a[2]), "r"(a[3]), "r"(b[0]), "r"(b[1]));
}

// ---------------- small utility kernels --------------------------------------
__global__ void k_zero_node(void) {
    int i = blockIdx.x * blockDim.x + threadIdx.x;
    if (i < Nn) { g_deg[i] = 0.f; g_cnt[i] = 0; }
}
__global__ void k_zero_pool(void) {
    int i = blockIdx.x * blockDim.x + threadIdx.x;
    if (i < NG * HID) g_pool[i] = 0.f;
    if (i < NG) g_pcnt[i] = 0.f;
}
__global__ void k_deg(const int* __restrict__ ei, const float* __restrict__ w) {
    int e = blockIdx.x * blockDim.x + threadIdx.x;
    if (e >= Ee) return;
    atomicAdd(&g_deg[ei[Ee + e]], w[e]);
}
__global__ void k_dinv(void) {
    int i = blockIdx.x * blockDim.x + threadIdx.x;
    if (i >= Nn) return;
    float d = g_deg[i];
    g_deg[i] = (d > 0.f) ? rsqrtf(d) : 0.f;
}
__global__ void k_norm_cnt(const int* __restrict__ ei, const float* __restrict__ w) {
    int e = blockIdx.x * blockDim.x + threadIdx.x;
    if (e >= Ee) return;
    int row = ei[e];
    int col = ei[Ee + e];
    g_norm[e] = g_deg[row] * w[e] * g_deg[col];
    atomicAdd(&g_cnt[col], 1);
}
__global__ void k_scan1(void) {
    __shared__ int s[1024];
    int t = threadIdx.x;
    int i = blockIdx.x * 1024 + t;
    s[t] = (i < Nn) ? g_cnt[i] : 0;
    __syncthreads();
    for (int d = 512; d > 0; d >>= 1) {
        if (t < d) s[t] += s[t + d];
        __syncthreads();
    }
    if (t == 0) g_psum[blockIdx.x] = s[0];
}
__global__ void k_scan2(void) {
    int run = 0;
    for (int b = 0; b < NB_SCAN; b++) { g_boff[b] = run; run += g_psum[b]; }
}
__global__ void k_scan3(void) {
    __shared__ int s[1024];
    int t = threadIdx.x;
    int i = blockIdx.x * 1024 + t;
    int v = (i < Nn) ? g_cnt[i] : 0;
    s[t] = v;
    __syncthreads();
    for (int d = 1; d < 1024; d <<= 1) {
        int add = (t >= d) ? s[t - d] : 0;
        __syncthreads();
        s[t] += add;
        __syncthreads();
    }
    if (i < Nn) {
        int excl = g_boff[blockIdx.x] + s[t] - v;
        g_off[i] = excl;
        g_cur[i] = excl;
    }
}
__global__ void k_scatter(const int* __restrict__ ei) {
    int e = blockIdx.x * blockDim.x + threadIdx.x;
    if (e >= Ee) return;
    int row = ei[e];
    int col = ei[Ee + e];
    int pos = atomicAdd(&g_cur[col], 1);
    g_src[pos] = row;
    g_nrm_s[pos] = g_norm[e];
}

// ---------------- bf16 split preps -------------------------------------------
__global__ void k_split_x(const float* __restrict__ x) {
    size_t i = (size_t)blockIdx.x * blockDim.x + threadIdx.x;
    if (i >= (size_t)Nn * 128) return;   // 2 elems each (256 cols)
    float2 v = ((const float2*)x)[i];
    __nv_bfloat16 h0 = __float2bfloat16(v.x);
    __nv_bfloat16 h1 = __float2bfloat16(v.y);
    __nv_bfloat16 l0 = __float2bfloat16(v.x - __bfloat162float(h0));
    __nv_bfloat16 l1 = __float2bfloat16(v.y - __bfloat162float(h1));
    ((__nv_bfloat162*)g_Ah0)[i] = __halves2bfloat162(h0, h1);
    ((__nv_bfloat162*)g_Al0)[i] = __halves2bfloat162(l0, l1);
}
template <bool FIRST>
__global__ void k_wsplit(const float* __restrict__ wi, const float* __restrict__ wr) {
    const int K = FIRST ? 256 : 128;
    int idx = blockIdx.x * blockDim.x + threadIdx.x;
    if (idx >= 256 * K) return;
    int n = idx / K, k = idx % K;
    float w = (n < 128) ? wi[k * 128 + n] : wr[k * 128 + (n - 128)];
    __nv_bfloat16 h = __float2bfloat16(w);
    __nv_bfloat16 l = __float2bfloat16(w - __bfloat162float(h));
    if (FIRST) { g_Bh0[idx] = h; g_Bl0[idx] = l; }
    else       { g_Bh1[idx] = h; g_Bl1[idx] = l; }
}

// ---------------- mma.sync GEMM: H[*,128] = A[M,K]@W (split-bf16, 3 phases) --
// CTA: 128x128 tile, 8 warps as 2x4 (warp tile 64x32), BK=32.
#define SROW 40   // smem row stride in bf16 (32 data + 8 pad) -> 80 bytes
template <bool FIRST>
__global__ void __launch_bounds__(256, 2) k_mma(void) {
    constexpr int K   = FIRST ? 256 : 128;
    constexpr int CPP = K / 32;          // chunks per phase
    constexpr int NC  = 3 * CPP;         // total K-chunks
    __shared__ __align__(16) __nv_bfloat16 sA[128 * SROW];
    __shared__ __align__(16) __nv_bfloat16 sB[128 * SROW];

    const __nv_bfloat16* Ah = FIRST ? g_Ah0 : g_Ah1;
    const __nv_bfloat16* Al = FIRST ? g_Al0 : g_Al1;
    const __nv_bfloat16* Bh = FIRST ? g_Bh0 : g_Bh1;
    const __nv_bfloat16* Bl = FIRST ? g_Bl0 : g_Bl1;

    int tid = threadIdx.x, lane = tid & 31, wid = tid >> 5;
    int warp_m = wid >> 2;               // 0..1
    int warp_n = wid & 3;                // 0..3
    int rowBase = blockIdx.x * 128;
    float* Hout = (blockIdx.y == 0) ? g_Hi : g_Hr;
    int nBase = blockIdx.y * 128;

    uint32_t aB = s2u(sA), bB = s2u(sB);

    float acc[4][4][4] = {};

    for (int c = 0; c < NC; ++c) {
        int phase = c / CPP;
        int k0 = (c - phase * CPP) * 32;
        const __nv_bfloat16* Aa = (phase == 1) ? Al : Ah;
        const __nv_bfloat16* Bb = (phase == 2) ? Bl : Bh;
        // load 128x32 A and B tiles (512 uint4 each)
        #pragma unroll
        for (int j = tid; j < 1024; j += 256) {
            int isB = j >= 512;
            int i = j & 511;
            int row = i >> 2, q = i & 3;           // q: 8-bf16 group
            const __nv_bfloat16* src;
            if (!isB) {
                int rg = rowBase + row;
                if (rg >= Nn) rg = Nn - 1;
                src = &Aa[(size_t)rg * K + k0 + q * 8];
            } else {
                src = &Bb[(size_t)(nBase + row) * K + k0 + q * 8];
            }
            uint4 v = *(const uint4*)src;
            *(uint4*)&((isB ? sB : sA)[row * SROW + q * 8]) = v;
        }
        __syncthreads();
        #pragma unroll
        for (int kk = 0; kk < 2; kk++) {
            int k16 = kk * 16;
            uint32_t a[4][4];
            #pragma unroll
            for (int mt = 0; mt < 4; mt++) {
                int row = warp_m * 64 + mt * 16 + (lane & 15);
                uint32_t addr = aB + (uint32_t)(row * SROW + k16 + (lane >> 4) * 8) * 2;
                ldm_x4(a[mt][0], a[mt][1], a[mt][2], a[mt][3], addr);
            }
            uint32_t b[4][2];
            #pragma unroll
            for (int nt = 0; nt < 4; nt++) {
                int row = warp_n * 32 + nt * 8 + (lane & 7);
                uint32_t addr = bB + (uint32_t)(row * SROW + k16 + ((lane >> 3) & 1) * 8) * 2;
                ldm_x2(b[nt][0], b[nt][1], addr);
            }
            #pragma unroll
            for (int mt = 0; mt < 4; mt++)
                #pragma unroll
                for (int nt = 0; nt < 4; nt++)
                    mma_bf16(acc[mt][nt], a[mt], b[nt]);
        }
        __syncthreads();
    }

    // epilogue: write fragments to global
    #pragma unroll
    for (int mt = 0; mt < 4; mt++) {
        int m0 = rowBase + warp_m * 64 + mt * 16 + (lane >> 2);
        int m1 = m0 + 8;
        #pragma unroll
        for (int nt = 0; nt < 4; nt++) {
            int col = warp_n * 32 + nt * 8 + (lane & 3) * 2;
            if (m0 < Nn) {
                float2 v = make_float2(acc[mt][nt][0], acc[mt][nt][1]);
                *(float2*)&Hout[(size_t)m0 * 128 + col] = v;
            }
            if (m1 < Nn) {
                float2 v = make_float2(acc[mt][nt][2], acc[mt][nt][3]);
                *(float2*)&Hout[(size_t)m1 * 128 + col] = v;
            }
        }
    }
}

// ---------------- Aggregation: warp per node ---------------------------------
// agg0: h = relu(sum norm*Hi[src] + Hr[n] + b)  -> split bf16 for conv1
__global__ void k_agg0(const float* __restrict__ bias) {
    int warp = threadIdx.x >> 5;
    int lane = threadIdx.x & 31;
    int n = blockIdx.x * 8 + warp;
    if (n >= Nn) return;
    int start = g_off[n];
    int cnt = g_cnt[n];
    float4 acc = make_float4(0.f, 0.f, 0.f, 0.f);
    for (int e = start; e < start + cnt; e++) {
        int s = g_src[e];
        float nm = g_nrm_s[e];
        float4 v = *(const float4*)&g_Hi[(size_t)s * 128 + lane * 4];
        acc.x += nm * v.x; acc.y += nm * v.y; acc.z += nm * v.z; acc.w += nm * v.w;
    }
    float4 r = *(const float4*)&g_Hr[(size_t)n * 128 + lane * 4];
    float4 b = *(const float4*)&bias[lane * 4];
    float o0 = fmaxf(acc.x + r.x + b.x, 0.f);
    float o1 = fmaxf(acc.y + r.y + b.y, 0.f);
    float o2 = fmaxf(acc.z + r.z + b.z, 0.f);
    float o3 = fmaxf(acc.w + r.w + b.w, 0.f);
    __nv_bfloat16 h0 = __float2bfloat16(o0), h1 = __float2bfloat16(o1);
    __nv_bfloat16 h2 = __float2bfloat16(o2), h3 = __float2bfloat16(o3);
    __nv_bfloat16 l0 = __float2bfloat16(o0 - __bfloat162float(h0));
    __nv_bfloat16 l1 = __float2bfloat16(o1 - __bfloat162float(h1));
    __nv_bfloat16 l2 = __float2bfloat16(o2 - __bfloat162float(h2));
    __nv_bfloat16 l3 = __float2bfloat16(o3 - __bfloat162float(h3));
    __nv_bfloat162* ph = (__nv_bfloat162*)&g_Ah1[(size_t)n * 128 + lane * 4];
    __nv_bfloat162* pl = (__nv_bfloat162*)&g_Al1[(size_t)n * 128 + lane * 4];
    ph[0] = __halves2bfloat162(h0, h1); ph[1] = __halves2bfloat162(h2, h3);
    pl[0] = __halves2bfloat162(l0, l1); pl[1] = __halves2bfloat162(l2, l3);
}

// agg1: conv1 aggregation + mean-pool atomics
__global__ void k_agg1(const float* __restrict__ bias, const int* __restrict__ batch) {
    int warp = threadIdx.x >> 5;
    int lane = threadIdx.x & 31;
    int n = blockIdx.x * 8 + warp;
    if (n >= Nn) return;
    int start = g_off[n];
    int cnt = g_cnt[n];
    float4 acc = make_float4(0.f, 0.f, 0.f, 0.f);
    for (int e = start; e < start + cnt; e++) {
        int s = g_src[e];
        float nm = g_nrm_s[e];
        float4 v = *(const float4*)&g_Hi[(size_t)s * 128 + lane * 4];
        acc.x += nm * v.x; acc.y += nm * v.y; acc.z += nm * v.z; acc.w += nm * v.w;
    }
    float4 r = *(const float4*)&g_Hr[(size_t)n * 128 + lane * 4];
    float4 b = *(const float4*)&bias[lane * 4];
    float4 o;
    o.x = fmaxf(acc.x + r.x + b.x, 0.f);
    o.y = fmaxf(acc.y + r.y + b.y, 0.f);
    o.z = fmaxf(acc.z + r.z + b.z, 0.f);
    o.w = fmaxf(acc.w + r.w + b.w, 0.f);
    int g = batch[n];
    float* p = &g_pool[(size_t)g * 128 + lane * 4];
    atomicAdd(p + 0, o.x);
    atomicAdd(p + 1, o.y);
    atomicAdd(p + 2, o.z);
    atomicAdd(p + 3, o.w);
    if (lane == 0) atomicAdd(&g_pcnt[g], 1.f);
}

// ---------------- pool finalize + MLP ----------------------------------------
__global__ void k_mlp(const float* __restrict__ w1, const float* __restrict__ b1,
                      const float* __restrict__ w2, const float* __restrict__ b2,
                      float* __restrict__ out) {
    __shared__ float gx[128];
    __shared__ float hid[256];
    int g = blockIdx.x;
    int t = threadIdx.x;
    if (t < 128) {
        float c = fmaxf(g_pcnt[g], 1.f);
        gx[t] = g_pool[(size_t)g * 128 + t] / c;
    }
    __syncthreads();
    float acc = b1[t];
    #pragma unroll 8
    for (int k = 0; k < 128; k++) acc += gx[k] * w1[k * 256 + t];
    hid[t] = fmaxf(acc, 0.f);
    __syncthreads();
    int warp = t >> 5, lane = t & 31;
    if (warp < 2) {
        int c = warp;
        float s = 0.f;
        for (int k = lane; k < 256; k += 32) s += hid[k] * w2[k * 2 + c];
        #pragma unroll
        for (int d = 16; d > 0; d >>= 1) s += __shfl_xor_sync(0xFFFFFFFF, s, d);
        if (lane == 0) out[g * 2 + c] = s + b2[c];
    }
}

// ---------------- launch -----------------------------------------------------
extern "C" void kernel_launch(void* const* d_in, const int* in_sizes, int n_in,
                              void* d_out, int out_size) {
    const float* x     = (const float*)d_in[0];
    const int*   ei    = (const int*)d_in[1];
    const float* ea    = (const float*)d_in[2];
    const int*   batch = (const int*)d_in[3];
    const float* w_init0 = (const float*)d_in[4];
    const float* w_root0 = (const float*)d_in[5];
    const float* b0      = (const float*)d_in[6];
    const float* w_init1 = (const float*)d_in[7];
    const float* w_root1 = (const float*)d_in[8];
    const float* b1      = (const float*)d_in[9];
    const float* mlp_w1  = (const float*)d_in[10];
    const float* mlp_b1  = (const float*)d_in[11];
    const float* mlp_w2  = (const float*)d_in[12];
    const float* mlp_b2  = (const float*)d_in[13];
    float* out = (float*)d_out;

    const int TB = 256;
    int nBlkN = (Nn + TB - 1) / TB;
    int nBlkE = (Ee + TB - 1) / TB;

    // norm + CSR build (reused by both convs)
    k_zero_node<<<nBlkN, TB>>>();
    k_zero_pool<<<(NG * HID + TB - 1) / TB, TB>>>();
    k_deg<<<nBlkE, TB>>>(ei, ea);
    k_dinv<<<nBlkN, TB>>>();
    k_norm_cnt<<<nBlkE, TB>>>(ei, ea);
    k_scan1<<<NB_SCAN, 1024>>>();
    k_scan2<<<1, 1>>>();
    k_scan3<<<NB_SCAN, 1024>>>();
    k_scatter<<<nBlkE, TB>>>(ei);

    // bf16 splits
    k_split_x<<<(Nn * 128 + TB - 1) / TB, TB>>>(x);
    k_wsplit<true><<<(256 * 256 + TB - 1) / TB, TB>>>(w_init0, w_root0);
    k_wsplit<false><<<(256 * 128 + TB - 1) / TB, TB>>>(w_init1, w_root1);

    dim3 gg((Nn + 127) / 128, 2);

    // conv0: mma GEMM + aggregation
    k_mma<true><<<gg, 256>>>();
    k_agg0<<<(Nn + 7) / 8, 256>>>(b0);

    // conv1
    k_mma<false><<<gg, 256>>>();
    k_agg1<<<(Nn + 7) / 8, 256>>>(b1, batch);

    // pool + MLP
    k_mlp<<<NG, 256>>>(mlp_w1, mlp_b1, mlp_w2, mlp_b2, out);
}

// round 6
// speedup vs baseline: 1.9015x; 1.0758x over previous
#include <cuda_runtime.h>
#include <cuda_bf16.h>
#include <cstdint>

// Problem constants
#define Nn   100000
#define Ee   1600000
#define HID  128
#define NG   512
#define NB_SCAN 98        // ceil(100000/1024)

// ---------------- scratch (static device memory) -----------------------------
__device__ __align__(128) float g_Hi[(size_t)Nn * 128];
__device__ __align__(128) float g_Hr[(size_t)Nn * 128];
__device__ __align__(128) __nv_bfloat16 g_Ah0[(size_t)Nn * 256];
__device__ __align__(128) __nv_bfloat16 g_Al0[(size_t)Nn * 256];
__device__ __align__(128) __nv_bfloat16 g_Ah1[(size_t)Nn * 128];
__device__ __align__(128) __nv_bfloat16 g_Al1[(size_t)Nn * 128];
__device__ __align__(128) __nv_bfloat16 g_Bh0[256 * 256];
__device__ __align__(128) __nv_bfloat16 g_Bl0[256 * 256];
__device__ __align__(128) __nv_bfloat16 g_Bh1[256 * 128];
__device__ __align__(128) __nv_bfloat16 g_Bl1[256 * 128];
__device__ float g_deg[Nn];
__device__ int   g_cnt[Nn];
__device__ int   g_off[Nn];
__device__ int   g_cur[Nn];
__device__ int   g_src[Ee];
__device__ float g_nrm_s[Ee];
__device__ int   g_psum[NB_SCAN];
__device__ int   g_boff[NB_SCAN];
__device__ float g_pool[NG * HID];
__device__ float g_pcnt[NG];

// ---------------- PTX helpers (base sm_100 features only) --------------------
__device__ __forceinline__ uint32_t s2u(const void* p) {
    uint32_t a;
    asm("{ .reg .u64 t; cvta.to.shared.u64 t, %1; cvt.u32.u64 %0, t; }" : "=r"(a) : "l"(p));
    return a;
}
__device__ __forceinline__ void ldm_x4(uint32_t& r0, uint32_t& r1, uint32_t& r2, uint32_t& r3,
                                       uint32_t addr) {
    asm volatile("ldmatrix.sync.aligned.m8n8.x4.shared.b16 {%0,%1,%2,%3}, [%4];"
                 : "=r"(r0), "=r"(r1), "=r"(r2), "=r"(r3) : "r"(addr));
}
__device__ __forceinline__ void ldm_x2(uint32_t& r0, uint32_t& r1, uint32_t addr) {
    asm volatile("ldmatrix.sync.aligned.m8n8.x2.shared.b16 {%0,%1}, [%2];"
                 : "=r"(r0), "=r"(r1) : "r"(addr));
}
__device__ __forceinline__ void mma_bf16(float* c, const uint32_t* a, const uint32_t* b) {
    asm volatile(
        "mma.sync.aligned.m16n8k16.row.col.f32.bf16.bf16.f32 "
        "{%0,%1,%2,%3}, {%4,%5,%6,%7}, {%8,%9}, {%0,%1,%2,%3};"
        : "+f"(c[0]), "+f"(c[1]), "+f"(c[2]), "+f"(c[3])
        : "r"(a[0]), "r"(a[1]), "r"(a[2]), "r"(a[3]), "r"(b[0]), "r"(b[1]));
}
__device__ __forceinline__ void cpa16(uint32_t saddr, const void* gaddr) {
    asm volatile("cp.async.cg.shared.global [%0], [%1], 16;" :: "r"(saddr), "l"(gaddr));
}
__device__ __forceinline__ void cpa_commit(void) {
    asm volatile("cp.async.commit_group;" ::: "memory");
}
template <int N>
__device__ __forceinline__ void cpa_wait(void) {
    asm volatile("cp.async.wait_group %0;" :: "n"(N) : "memory");
}

// ---------------- fused zero + CSR build kernels ------------------------------
__global__ void k_zero(void) {
    int i = blockIdx.x * blockDim.x + threadIdx.x;
    if (i < Nn) { g_deg[i] = 0.f; g_cnt[i] = 0; }
    if (i < NG * HID) g_pool[i] = 0.f;
    if (i < NG) g_pcnt[i] = 0.f;
}
__global__ void k_degcnt(const int* __restrict__ ei, const float* __restrict__ w) {
    int e = blockIdx.x * blockDim.x + threadIdx.x;
    if (e >= Ee) return;
    int col = ei[Ee + e];
    atomicAdd(&g_deg[col], w[e]);
    atomicAdd(&g_cnt[col], 1);
}
__global__ void k_dinv(void) {
    int i = blockIdx.x * blockDim.x + threadIdx.x;
    if (i >= Nn) return;
    float d = g_deg[i];
    g_deg[i] = (d > 0.f) ? rsqrtf(d) : 0.f;
}
__global__ void k_scan1(void) {
    __shared__ int s[1024];
    int t = threadIdx.x;
    int i = blockIdx.x * 1024 + t;
    s[t] = (i < Nn) ? g_cnt[i] : 0;
    __syncthreads();
    for (int d = 512; d > 0; d >>= 1) {
        if (t < d) s[t] += s[t + d];
        __syncthreads();
    }
    if (t == 0) g_psum[blockIdx.x] = s[0];
}
__global__ void k_scan2(void) {
    int run = 0;
    for (int b = 0; b < NB_SCAN; b++) { g_boff[b] = run; run += g_psum[b]; }
}
__global__ void k_scan3(void) {
    __shared__ int s[1024];
    int t = threadIdx.x;
    int i = blockIdx.x * 1024 + t;
    int v = (i < Nn) ? g_cnt[i] : 0;
    s[t] = v;
    __syncthreads();
    for (int d = 1; d < 1024; d <<= 1) {
        int add = (t >= d) ? s[t - d] : 0;
        __syncthreads();
        s[t] += add;
        __syncthreads();
    }
    if (i < Nn) {
        int excl = g_boff[blockIdx.x] + s[t] - v;
        g_off[i] = excl;
        g_cur[i] = excl;
    }
}
// scatter with fused norm computation
__global__ void k_scatter(const int* __restrict__ ei, const float* __restrict__ w) {
    int e = blockIdx.x * blockDim.x + threadIdx.x;
    if (e >= Ee) return;
    int row = ei[e];
    int col = ei[Ee + e];
    int pos = atomicAdd(&g_cur[col], 1);
    g_src[pos] = row;
    g_nrm_s[pos] = g_deg[row] * w[e] * g_deg[col];
}

// ---------------- bf16 split preps -------------------------------------------
__global__ void k_split_x(const float* __restrict__ x) {
    size_t i = (size_t)blockIdx.x * blockDim.x + threadIdx.x;
    if (i >= (size_t)Nn * 128) return;
    float2 v = ((const float2*)x)[i];
    __nv_bfloat16 h0 = __float2bfloat16(v.x);
    __nv_bfloat16 h1 = __float2bfloat16(v.y);
    __nv_bfloat16 l0 = __float2bfloat16(v.x - __bfloat162float(h0));
    __nv_bfloat16 l1 = __float2bfloat16(v.y - __bfloat162float(h1));
    ((__nv_bfloat162*)g_Ah0)[i] = __halves2bfloat162(h0, h1);
    ((__nv_bfloat162*)g_Al0)[i] = __halves2bfloat162(l0, l1);
}
template <bool FIRST>
__global__ void k_wsplit(const float* __restrict__ wi, const float* __restrict__ wr) {
    const int K = FIRST ? 256 : 128;
    int idx = blockIdx.x * blockDim.x + threadIdx.x;
    if (idx >= 256 * K) return;
    int n = idx / K, k = idx % K;
    float w = (n < 128) ? wi[k * 128 + n] : wr[k * 128 + (n - 128)];
    __nv_bfloat16 h = __float2bfloat16(w);
    __nv_bfloat16 l = __float2bfloat16(w - __bfloat162float(h));
    if (FIRST) { g_Bh0[idx] = h; g_Bl0[idx] = l; }
    else       { g_Bh1[idx] = h; g_Bl1[idx] = l; }
}

// ---------------- pipelined mma.sync GEMM ------------------------------------
// CTA 128x128 tile, 8 warps 2x4 (warp tile 64x32), BK=32, double-buffered cp.async.
#define SROW 40   // smem row stride in bf16 (32 data + 8 pad) -> 80 bytes
template <bool FIRST>
__global__ void __launch_bounds__(256, 2) k_mma(void) {
    constexpr int K   = FIRST ? 256 : 128;
    constexpr int CPP = K / 32;
    constexpr int NC  = 3 * CPP;
    __shared__ __align__(16) __nv_bfloat16 sA[2][128 * SROW];
    __shared__ __align__(16) __nv_bfloat16 sB[2][128 * SROW];

    const __nv_bfloat16* Ah = FIRST ? g_Ah0 : g_Ah1;
    const __nv_bfloat16* Al = FIRST ? g_Al0 : g_Al1;
    const __nv_bfloat16* Bh = FIRST ? g_Bh0 : g_Bh1;
    const __nv_bfloat16* Bl = FIRST ? g_Bl0 : g_Bl1;

    int tid = threadIdx.x, lane = tid & 31, wid = tid >> 5;
    int warp_m = wid >> 2;
    int warp_n = wid & 3;
    int rowBase = blockIdx.x * 128;
    float* Hout = (blockIdx.y == 0) ? g_Hi : g_Hr;
    int nBase = blockIdx.y * 128;

    // per-thread fixed load slots: 4 x 16B (2 A rows-halves + 2 B)
    // j = tid + 256*t over [0,1024): first 512 A, next 512 B
    auto issue_chunk = [&](int c, int buf) {
        int phase = c / CPP;
        int k0 = (c - phase * CPP) * 32;
        const __nv_bfloat16* Aa = (phase == 1) ? Al : Ah;
        const __nv_bfloat16* Bb = (phase == 2) ? Bl : Bh;
        #pragma unroll
        for (int j = tid; j < 1024; j += 256) {
            int isB = j >= 512;
            int i = j & 511;
            int row = i >> 2, q = i & 3;
            const __nv_bfloat16* src;
            if (!isB) {
                int rg = rowBase + row;
                if (rg >= Nn) rg = Nn - 1;
                src = &Aa[(size_t)rg * K + k0 + q * 8];
            } else {
                src = &Bb[(size_t)(nBase + row) * K + k0 + q * 8];
            }
            uint32_t dst = s2u(&(isB ? sB : sA)[buf][row * SROW + q * 8]);
            cpa16(dst, src);
        }
        cpa_commit();
    };

    float acc[4][4][4] = {};

    issue_chunk(0, 0);
    for (int c = 0; c < NC; ++c) {
        int buf = c & 1;
        cpa_wait<0>();          // only chunk c's group may be outstanding here? see below
        __syncthreads();
        if (c + 1 < NC) issue_chunk(c + 1, buf ^ 1);
        uint32_t aB = s2u(&sA[buf][0]), bB = s2u(&sB[buf][0]);
        #pragma unroll
        for (int kk = 0; kk < 2; kk++) {
            int k16 = kk * 16;
            uint32_t a[4][4];
            #pragma unroll
            for (int mt = 0; mt < 4; mt++) {
                int row = warp_m * 64 + mt * 16 + (lane & 15);
                uint32_t addr = aB + (uint32_t)(row * SROW + k16 + (lane >> 4) * 8) * 2;
                ldm_x4(a[mt][0], a[mt][1], a[mt][2], a[mt][3], addr);
            }
            uint32_t b[4][2];
            #pragma unroll
            for (int nt = 0; nt < 4; nt++) {
                int row = warp_n * 32 + nt * 8 + (lane & 7);
                uint32_t addr = bB + (uint32_t)(row * SROW + k16 + ((lane >> 3) & 1) * 8) * 2;
                ldm_x2(b[nt][0], b[nt][1], addr);
            }
            #pragma unroll
            for (int mt = 0; mt < 4; mt++)
                #pragma unroll
                for (int nt = 0; nt < 4; nt++)
                    mma_bf16(acc[mt][nt], a[mt], b[nt]);
        }
        __syncthreads();
    }
    // NOTE on cpa_wait<0>: at top of iter c, groups outstanding = {c} (c+1 not yet
    // issued), so wait_group 0 waits exactly for chunk c. The issue for c+1 happens
    // after the barrier, writing the other buffer, whose readers finished at the
    // end of iter c-1 (barrier-protected).

    #pragma unroll
    for (int mt = 0; mt < 4; mt++) {
        int m0 = rowBase + warp_m * 64 + mt * 16 + (lane >> 2);
        int m1 = m0 + 8;
        #pragma unroll
        for (int nt = 0; nt < 4; nt++) {
            int col = warp_n * 32 + nt * 8 + (lane & 3) * 2;
            if (m0 < Nn) {
                float2 v = make_float2(acc[mt][nt][0], acc[mt][nt][1]);
                *(float2*)&Hout[(size_t)m0 * 128 + col] = v;
            }
            if (m1 < Nn) {
                float2 v = make_float2(acc[mt][nt][2], acc[mt][nt][3]);
                *(float2*)&Hout[(size_t)m1 * 128 + col] = v;
            }
        }
    }
}

// ---------------- Aggregation: warp per node (edge loop unrolled x2) ---------
__global__ void k_agg0(const float* __restrict__ bias) {
    int warp = threadIdx.x >> 5;
    int lane = threadIdx.x & 31;
    int n = blockIdx.x * 8 + warp;
    if (n >= Nn) return;
    int e = g_off[n];
    int end = e + g_cnt[n];
    float4 acc = make_float4(0.f, 0.f, 0.f, 0.f);
    for (; e + 1 < end; e += 2) {
        int s0 = g_src[e], s1 = g_src[e + 1];
        float n0 = g_nrm_s[e], n1 = g_nrm_s[e + 1];
        float4 v0 = *(const float4*)&g_Hi[(size_t)s0 * 128 + lane * 4];
        float4 v1 = *(const float4*)&g_Hi[(size_t)s1 * 128 + lane * 4];
        acc.x += n0 * v0.x + n1 * v1.x;
        acc.y += n0 * v0.y + n1 * v1.y;
        acc.z += n0 * v0.z + n1 * v1.z;
        acc.w += n0 * v0.w + n1 * v1.w;
    }
    if (e < end) {
        int s0 = g_src[e];
        float n0 = g_nrm_s[e];
        float4 v0 = *(const float4*)&g_Hi[(size_t)s0 * 128 + lane * 4];
        acc.x += n0 * v0.x; acc.y += n0 * v0.y; acc.z += n0 * v0.z; acc.w += n0 * v0.w;
    }
    float4 r = *(const float4*)&g_Hr[(size_t)n * 128 + lane * 4];
    float4 b = *(const float4*)&bias[lane * 4];
    float o0 = fmaxf(acc.x + r.x + b.x, 0.f);
    float o1 = fmaxf(acc.y + r.y + b.y, 0.f);
    float o2 = fmaxf(acc.z + r.z + b.z, 0.f);
    float o3 = fmaxf(acc.w + r.w + b.w, 0.f);
    __nv_bfloat16 h0 = __float2bfloat16(o0), h1 = __float2bfloat16(o1);
    __nv_bfloat16 h2 = __float2bfloat16(o2), h3 = __float2bfloat16(o3);
    __nv_bfloat16 l0 = __float2bfloat16(o0 - __bfloat162float(h0));
    __nv_bfloat16 l1 = __float2bfloat16(o1 - __bfloat162float(h1));
    __nv_bfloat16 l2 = __float2bfloat16(o2 - __bfloat162float(h2));
    __nv_bfloat16 l3 = __float2bfloat16(o3 - __bfloat162float(h3));
    __nv_bfloat162* ph = (__nv_bfloat162*)&g_Ah1[(size_t)n * 128 + lane * 4];
    __nv_bfloat162* pl = (__nv_bfloat162*)&g_Al1[(size_t)n * 128 + lane * 4];
    ph[0] = __halves2bfloat162(h0, h1); ph[1] = __halves2bfloat162(h2, h3);
    pl[0] = __halves2bfloat162(l0, l1); pl[1] = __halves2bfloat162(l2, l3);
}

__global__ void k_agg1(const float* __restrict__ bias, const int* __restrict__ batch) {
    int warp = threadIdx.x >> 5;
    int lane = threadIdx.x & 31;
    int n = blockIdx.x * 8 + warp;
    if (n >= Nn) return;
    int e = g_off[n];
    int end = e + g_cnt[n];
    float4 acc = make_float4(0.f, 0.f, 0.f, 0.f);
    for (; e + 1 < end; e += 2) {
        int s0 = g_src[e], s1 = g_src[e + 1];
        float n0 = g_nrm_s[e], n1 = g_nrm_s[e + 1];
        float4 v0 = *(const float4*)&g_Hi[(size_t)s0 * 128 + lane * 4];
        float4 v1 = *(const float4*)&g_Hi[(size_t)s1 * 128 + lane * 4];
        acc.x += n0 * v0.x + n1 * v1.x;
        acc.y += n0 * v0.y + n1 * v1.y;
        acc.z += n0 * v0.z + n1 * v1.z;
        acc.w += n0 * v0.w + n1 * v1.w;
    }
    if (e < end) {
        int s0 = g_src[e];
        float n0 = g_nrm_s[e];
        float4 v0 = *(const float4*)&g_Hi[(size_t)s0 * 128 + lane * 4];
        acc.x += n0 * v0.x; acc.y += n0 * v0.y; acc.z += n0 * v0.z; acc.w += n0 * v0.w;
    }
    float4 r = *(const float4*)&g_Hr[(size_t)n * 128 + lane * 4];
    float4 b = *(const float4*)&bias[lane * 4];
    float4 o;
    o.x = fmaxf(acc.x + r.x + b.x, 0.f);
    o.y = fmaxf(acc.y + r.y + b.y, 0.f);
    o.z = fmaxf(acc.z + r.z + b.z, 0.f);
    o.w = fmaxf(acc.w + r.w + b.w, 0.f);
    int g = batch[n];
    float* p = &g_pool[(size_t)g * 128 + lane * 4];
    atomicAdd(p + 0, o.x);
    atomicAdd(p + 1, o.y);
    atomicAdd(p + 2, o.z);
    atomicAdd(p + 3, o.w);
    if (lane == 0) atomicAdd(&g_pcnt[g], 1.f);
}

// ---------------- pool finalize + MLP ----------------------------------------
__global__ void k_mlp(const float* __restrict__ w1, const float* __restrict__ b1,
                      const float* __restrict__ w2, const float* __restrict__ b2,
                      float* __restrict__ out) {
    __shared__ float gx[128];
    __shared__ float hid[256];
    int g = blockIdx.x;
    int t = threadIdx.x;
    if (t < 128) {
        float c = fmaxf(g_pcnt[g], 1.f);
        gx[t] = g_pool[(size_t)g * 128 + t] / c;
    }
    __syncthreads();
    float acc = b1[t];
    #pragma unroll 8
    for (int k = 0; k < 128; k++) acc += gx[k] * w1[k * 256 + t];
    hid[t] = fmaxf(acc, 0.f);
    __syncthreads();
    int warp = t >> 5, lane = t & 31;
    if (warp < 2) {
        int c = warp;
        float s = 0.f;
        for (int k = lane; k < 256; k += 32) s += hid[k] * w2[k * 2 + c];
        #pragma unroll
        for (int d = 16; d > 0; d >>= 1) s += __shfl_xor_sync(0xFFFFFFFF, s, d);
        if (lane == 0) out[g * 2 + c] = s + b2[c];
    }
}

// ---------------- launch (fork-join: CSR build overlaps split+GEMM0) ----------
extern "C" void kernel_launch(void* const* d_in, const int* in_sizes, int n_in,
                              void* d_out, int out_size) {
    const float* x     = (const float*)d_in[0];
    const int*   ei    = (const int*)d_in[1];
    const float* ea    = (const float*)d_in[2];
    const int*   batch = (const int*)d_in[3];
    const float* w_init0 = (const float*)d_in[4];
    const float* w_root0 = (const float*)d_in[5];
    const float* b0      = (const float*)d_in[6];
    const float* w_init1 = (const float*)d_in[7];
    const float* w_root1 = (const float*)d_in[8];
    const float* b1      = (const float*)d_in[9];
    const float* mlp_w1  = (const float*)d_in[10];
    const float* mlp_b1  = (const float*)d_in[11];
    const float* mlp_w2  = (const float*)d_in[12];
    const float* mlp_b2  = (const float*)d_in[13];
    float* out = (float*)d_out;

    const int TB = 256;
    int nBlkN = (Nn + TB - 1) / TB;
    int nBlkE = (Ee + TB - 1) / TB;
    dim3 gg((Nn + 127) / 128, 2);

    cudaStream_t s2;
    cudaEvent_t evFork, evJoin;
    bool forked = (cudaStreamCreateWithFlags(&s2, cudaStreamNonBlocking) == cudaSuccess) &&
                  (cudaEventCreateWithFlags(&evFork, cudaEventDisableTiming) == cudaSuccess) &&
                  (cudaEventCreateWithFlags(&evJoin, cudaEventDisableTiming) == cudaSuccess);

    if (forked && cudaEventRecord(evFork, 0) == cudaSuccess &&
        cudaStreamWaitEvent(s2, evFork, 0) == cudaSuccess) {
        // side branch: CSR build
        int nz = ((NG * HID > Nn ? NG * HID : Nn) + TB - 1) / TB;
        k_zero<<<nz, TB, 0, s2>>>();
        k_degcnt<<<nBlkE, TB, 0, s2>>>(ei, ea);
        k_dinv<<<nBlkN, TB, 0, s2>>>();
        k_scan1<<<NB_SCAN, 1024, 0, s2>>>();
        k_scan2<<<1, 1, 0, s2>>>();
        k_scan3<<<NB_SCAN, 1024, 0, s2>>>();
        k_scatter<<<nBlkE, TB, 0, s2>>>(ei, ea);
        cudaEventRecord(evJoin, s2);

        // main branch: splits + GEMM0
        k_split_x<<<(Nn * 128 + TB - 1) / TB, TB>>>(x);
        k_wsplit<true><<<(256 * 256 + TB - 1) / TB, TB>>>(w_init0, w_root0);
        k_wsplit<false><<<(256 * 128 + TB - 1) / TB, TB>>>(w_init1, w_root1);
        k_mma<true><<<gg, 256>>>();

        cudaStreamWaitEvent(0, evJoin, 0);   // join before agg0
    } else {
        // fallback: serial on default stream
        int nz = ((NG * HID > Nn ? NG * HID : Nn) + TB - 1) / TB;
        k_zero<<<nz, TB>>>();
        k_degcnt<<<nBlkE, TB>>>(ei, ea);
        k_dinv<<<nBlkN, TB>>>();
        k_scan1<<<NB_SCAN, 1024>>>();
        k_scan2<<<1, 1>>>();
        k_scan3<<<NB_SCAN, 1024>>>();
        k_scatter<<<nBlkE, TB>>>(ei, ea);
        k_split_x<<<(Nn * 128 + TB - 1) / TB, TB>>>(x);
        k_wsplit<true><<<(256 * 256 + TB - 1) / TB, TB>>>(w_init0, w_root0);
        k_wsplit<false><<<(256 * 128 + TB - 1) / TB, TB>>>(w_init1, w_root1);
        k_mma<true><<<gg, 256>>>();
    }

    k_agg0<<<(Nn + 7) / 8, 256>>>(b0);
    k_mma<false><<<gg, 256>>>();
    k_agg1<<<(Nn + 7) / 8, 256>>>(b1, batch);
    k_mlp<<<NG, 256>>>(mlp_w1, mlp_b1, mlp_w2, mlp_b2, out);

    if (forked) {
        cudaStreamDestroy(s2);
        cudaEventDestroy(evFork);
        cudaEventDestroy(evJoin);
    }
}

// round 7
// speedup vs baseline: 2.1422x; 1.1266x over previous
#include <cuda_runtime.h>
#include <cuda_fp16.h>
#include <cstdint>

// Problem constants
#define Nn   100000
#define Ee   1600000
#define HID  128
#define NG   512
#define NB_SCAN 98        // ceil(100000/1024)

// ---------------- scratch (static device memory) -----------------------------
__device__ __align__(128) float g_Hi[(size_t)Nn * 128];
__device__ __align__(128) float g_Hr[(size_t)Nn * 128];
__device__ __align__(128) __half g_Ah0[(size_t)Nn * 256];
__device__ __align__(128) __half g_Al0[(size_t)Nn * 256];
__device__ __align__(128) __half g_Ah1[(size_t)Nn * 128];
__device__ __align__(128) __half g_Al1[(size_t)Nn * 128];
__device__ __align__(128) __half g_B0[256 * 256];
__device__ __align__(128) __half g_B1[256 * 128];
__device__ float g_deg[Nn];
__device__ int   g_cnt[Nn];
__device__ int   g_off[Nn];
__device__ int   g_cur[Nn];
__device__ int   g_src[Ee];
__device__ float g_nrm_s[Ee];
__device__ int   g_psum[NB_SCAN];
__device__ int   g_boff[NB_SCAN];
__device__ float g_pool[NG * HID];
__device__ float g_pcnt[NG];

// ---------------- PTX helpers (base sm_100 features only) --------------------
__device__ __forceinline__ uint32_t s2u(const void* p) {
    uint32_t a;
    asm("{ .reg .u64 t; cvta.to.shared.u64 t, %1; cvt.u32.u64 %0, t; }" : "=r"(a) : "l"(p));
    return a;
}
__device__ __forceinline__ void ldm_x4(uint32_t& r0, uint32_t& r1, uint32_t& r2, uint32_t& r3,
                                       uint32_t addr) {
    asm volatile("ldmatrix.sync.aligned.m8n8.x4.shared.b16 {%0,%1,%2,%3}, [%4];"
                 : "=r"(r0), "=r"(r1), "=r"(r2), "=r"(r3) : "r"(addr));
}
__device__ __forceinline__ void ldm_x2(uint32_t& r0, uint32_t& r1, uint32_t addr) {
    asm volatile("ldmatrix.sync.aligned.m8n8.x2.shared.b16 {%0,%1}, [%2];"
                 : "=r"(r0), "=r"(r1) : "r"(addr));
}
__device__ __forceinline__ void mma_f16(float* c, const uint32_t* a, const uint32_t* b) {
    asm volatile(
        "mma.sync.aligned.m16n8k16.row.col.f32.f16.f16.f32 "
        "{%0,%1,%2,%3}, {%4,%5,%6,%7}, {%8,%9}, {%0,%1,%2,%3};"
        : "+f"(c[0]), "+f"(c[1]), "+f"(c[2]), "+f"(c[3])
        : "r"(a[0]), "r"(a[1]), "r"(a[2]), "r"(a[3]), "r"(b[0]), "r"(b[1]));
}
__device__ __forceinline__ void cpa16(uint32_t saddr, const void* gaddr) {
    asm volatile("cp.async.cg.shared.global [%0], [%1], 16;" :: "r"(saddr), "l"(gaddr));
}
__device__ __forceinline__ void cpa_commit(void) {
    asm volatile("cp.async.commit_group;" ::: "memory");
}
template <int N>
__device__ __forceinline__ void cpa_wait(void) {
    asm volatile("cp.async.wait_group %0;" :: "n"(N) : "memory");
}

// ---------------- fused zero + CSR build kernels ------------------------------
__global__ void k_zero(void) {
    int i = blockIdx.x * blockDim.x + threadIdx.x;
    if (i < Nn) { g_deg[i] = 0.f; g_cnt[i] = 0; }
    if (i < NG * HID) g_pool[i] = 0.f;
    if (i < NG) g_pcnt[i] = 0.f;
}
__global__ void k_degcnt(const int* __restrict__ ei, const float* __restrict__ w) {
    int e = blockIdx.x * blockDim.x + threadIdx.x;
    if (e >= Ee) return;
    int col = ei[Ee + e];
    atomicAdd(&g_deg[col], w[e]);
    atomicAdd(&g_cnt[col], 1);
}
// scan1 with fused dinv (independent data, saves a launch)
__global__ void k_scan1(void) {
    __shared__ int s[1024];
    int t = threadIdx.x;
    int i = blockIdx.x * 1024 + t;
    if (i < Nn) {
        float d = g_deg[i];
        g_deg[i] = (d > 0.f) ? rsqrtf(d) : 0.f;
    }
    s[t] = (i < Nn) ? g_cnt[i] : 0;
    __syncthreads();
    for (int d = 512; d > 0; d >>= 1) {
        if (t < d) s[t] += s[t + d];
        __syncthreads();
    }
    if (t == 0) g_psum[blockIdx.x] = s[0];
}
__global__ void k_scan2(void) {
    int run = 0;
    for (int b = 0; b < NB_SCAN; b++) { g_boff[b] = run; run += g_psum[b]; }
}
__global__ void k_scan3(void) {
    __shared__ int s[1024];
    int t = threadIdx.x;
    int i = blockIdx.x * 1024 + t;
    int v = (i < Nn) ? g_cnt[i] : 0;
    s[t] = v;
    __syncthreads();
    for (int d = 1; d < 1024; d <<= 1) {
        int add = (t >= d) ? s[t - d] : 0;
        __syncthreads();
        s[t] += add;
        __syncthreads();
    }
    if (i < Nn) {
        int excl = g_boff[blockIdx.x] + s[t] - v;
        g_off[i] = excl;
        g_cur[i] = excl;
    }
}
__global__ void k_scatter(const int* __restrict__ ei, const float* __restrict__ w) {
    int e = blockIdx.x * blockDim.x + threadIdx.x;
    if (e >= Ee) return;
    int row = ei[e];
    int col = ei[Ee + e];
    int pos = atomicAdd(&g_cur[col], 1);
    g_src[pos] = row;
    g_nrm_s[pos] = g_deg[row] * w[e] * g_deg[col];
}

// ---------------- fp16 split preps -------------------------------------------
__global__ void k_split_x(const float* __restrict__ x) {
    size_t i = (size_t)blockIdx.x * blockDim.x + threadIdx.x;
    if (i >= (size_t)Nn * 128) return;
    float2 v = ((const float2*)x)[i];
    __half h0 = __float2half(v.x);
    __half h1 = __float2half(v.y);
    __half l0 = __float2half(v.x - __half2float(h0));
    __half l1 = __float2half(v.y - __half2float(h1));
    ((__half2*)g_Ah0)[i] = __halves2half2(h0, h1);
    ((__half2*)g_Al0)[i] = __halves2half2(l0, l1);
}
template <bool FIRST>
__global__ void k_wsplit(const float* __restrict__ wi, const float* __restrict__ wr) {
    const int K = FIRST ? 256 : 128;
    int idx = blockIdx.x * blockDim.x + threadIdx.x;
    if (idx >= 256 * K) return;
    int n = idx / K, k = idx % K;
    float w = (n < 128) ? wi[k * 128 + n] : wr[k * 128 + (n - 128)];
    if (FIRST) g_B0[idx] = __float2half(w);
    else       g_B1[idx] = __float2half(w);
}

// ---------------- pipelined mma.sync GEMM (2-phase fp16: Ah*B + Al*B) --------
#define SROW 40   // smem row stride in halves (32 data + 8 pad) -> 80 bytes
template <bool FIRST>
__global__ void __launch_bounds__(256, 2) k_mma(void) {
    constexpr int K   = FIRST ? 256 : 128;
    constexpr int CPP = K / 32;
    constexpr int NC  = 2 * CPP;
    __shared__ __align__(16) __half sA[2][128 * SROW];
    __shared__ __align__(16) __half sB[2][128 * SROW];

    const __half* Ah = FIRST ? g_Ah0 : g_Ah1;
    const __half* Al = FIRST ? g_Al0 : g_Al1;
    const __half* Bw = FIRST ? g_B0 : g_B1;

    int tid = threadIdx.x, lane = tid & 31, wid = tid >> 5;
    int warp_m = wid >> 2;
    int warp_n = wid & 3;
    int rowBase = blockIdx.x * 128;
    float* Hout = (blockIdx.y == 0) ? g_Hi : g_Hr;
    int nBase = blockIdx.y * 128;

    auto issue_chunk = [&](int c, int buf) {
        int phase = c / CPP;
        int k0 = (c - phase * CPP) * 32;
        const __half* Aa = (phase == 1) ? Al : Ah;
        #pragma unroll
        for (int j = tid; j < 1024; j += 256) {
            int isB = j >= 512;
            int i = j & 511;
            int row = i >> 2, q = i & 3;
            const __half* src;
            if (!isB) {
                int rg = rowBase + row;
                if (rg >= Nn) rg = Nn - 1;
                src = &Aa[(size_t)rg * K + k0 + q * 8];
            } else {
                src = &Bw[(size_t)(nBase + row) * K + k0 + q * 8];
            }
            uint32_t dst = s2u(&(isB ? sB : sA)[buf][row * SROW + q * 8]);
            cpa16(dst, src);
        }
        cpa_commit();
    };

    float acc[4][4][4] = {};

    issue_chunk(0, 0);
    for (int c = 0; c < NC; ++c) {
        int buf = c & 1;
        cpa_wait<0>();
        __syncthreads();
        if (c + 1 < NC) issue_chunk(c + 1, buf ^ 1);
        uint32_t aB = s2u(&sA[buf][0]), bB = s2u(&sB[buf][0]);
        #pragma unroll
        for (int kk = 0; kk < 2; kk++) {
            int k16 = kk * 16;
            uint32_t a[4][4];
            #pragma unroll
            for (int mt = 0; mt < 4; mt++) {
                int row = warp_m * 64 + mt * 16 + (lane & 15);
                uint32_t addr = aB + (uint32_t)(row * SROW + k16 + (lane >> 4) * 8) * 2;
                ldm_x4(a[mt][0], a[mt][1], a[mt][2], a[mt][3], addr);
            }
            uint32_t b[4][2];
            #pragma unroll
            for (int nt = 0; nt < 4; nt++) {
                int row = warp_n * 32 + nt * 8 + (lane & 7);
                uint32_t addr = bB + (uint32_t)(row * SROW + k16 + ((lane >> 3) & 1) * 8) * 2;
                ldm_x2(b[nt][0], b[nt][1], addr);
            }
            #pragma unroll
            for (int mt = 0; mt < 4; mt++)
                #pragma unroll
                for (int nt = 0; nt < 4; nt++)
                    mma_f16(acc[mt][nt], a[mt], b[nt]);
        }
        __syncthreads();
    }

    #pragma unroll
    for (int mt = 0; mt < 4; mt++) {
        int m0 = rowBase + warp_m * 64 + mt * 16 + (lane >> 2);
        int m1 = m0 + 8;
        #pragma unroll
        for (int nt = 0; nt < 4; nt++) {
            int col = warp_n * 32 + nt * 8 + (lane & 3) * 2;
            if (m0 < Nn) {
                float2 v = make_float2(acc[mt][nt][0], acc[mt][nt][1]);
                *(float2*)&Hout[(size_t)m0 * 128 + col] = v;
            }
            if (m1 < Nn) {
                float2 v = make_float2(acc[mt][nt][2], acc[mt][nt][3]);
                *(float2*)&Hout[(size_t)m1 * 128 + col] = v;
            }
        }
    }
}

// ---------------- Aggregation: warp per node ---------------------------------
__global__ void k_agg0(const float* __restrict__ bias) {
    int warp = threadIdx.x >> 5;
    int lane = threadIdx.x & 31;
    int n = blockIdx.x * 8 + warp;
    if (n >= Nn) return;
    int e = g_off[n];
    int end = e + g_cnt[n];
    float4 acc = make_float4(0.f, 0.f, 0.f, 0.f);
    for (; e + 1 < end; e += 2) {
        int s0 = g_src[e], s1 = g_src[e + 1];
        float n0 = g_nrm_s[e], n1 = g_nrm_s[e + 1];
        float4 v0 = *(const float4*)&g_Hi[(size_t)s0 * 128 + lane * 4];
        float4 v1 = *(const float4*)&g_Hi[(size_t)s1 * 128 + lane * 4];
        acc.x += n0 * v0.x + n1 * v1.x;
        acc.y += n0 * v0.y + n1 * v1.y;
        acc.z += n0 * v0.z + n1 * v1.z;
        acc.w += n0 * v0.w + n1 * v1.w;
    }
    if (e < end) {
        int s0 = g_src[e];
        float n0 = g_nrm_s[e];
        float4 v0 = *(const float4*)&g_Hi[(size_t)s0 * 128 + lane * 4];
        acc.x += n0 * v0.x; acc.y += n0 * v0.y; acc.z += n0 * v0.z; acc.w += n0 * v0.w;
    }
    float4 r = *(const float4*)&g_Hr[(size_t)n * 128 + lane * 4];
    float4 b = *(const float4*)&bias[lane * 4];
    float o0 = fmaxf(acc.x + r.x + b.x, 0.f);
    float o1 = fmaxf(acc.y + r.y + b.y, 0.f);
    float o2 = fmaxf(acc.z + r.z + b.z, 0.f);
    float o3 = fmaxf(acc.w + r.w + b.w, 0.f);
    __half h0 = __float2half(o0), h1 = __float2half(o1);
    __half h2 = __float2half(o2), h3 = __float2half(o3);
    __half l0 = __float2half(o0 - __half2float(h0));
    __half l1 = __float2half(o1 - __half2float(h1));
    __half l2 = __float2half(o2 - __half2float(h2));
    __half l3 = __float2half(o3 - __half2float(h3));
    __half2* ph = (__half2*)&g_Ah1[(size_t)n * 128 + lane * 4];
    __half2* pl = (__half2*)&g_Al1[(size_t)n * 128 + lane * 4];
    ph[0] = __halves2half2(h0, h1); ph[1] = __halves2half2(h2, h3);
    pl[0] = __halves2half2(l0, l1); pl[1] = __halves2half2(l2, l3);
}

__global__ void k_agg1(const float* __restrict__ bias, const int* __restrict__ batch) {
    int warp = threadIdx.x >> 5;
    int lane = threadIdx.x & 31;
    int n = blockIdx.x * 8 + warp;
    if (n >= Nn) return;
    int e = g_off[n];
    int end = e + g_cnt[n];
    float4 acc = make_float4(0.f, 0.f, 0.f, 0.f);
    for (; e + 1 < end; e += 2) {
        int s0 = g_src[e], s1 = g_src[e + 1];
        float n0 = g_nrm_s[e], n1 = g_nrm_s[e + 1];
        float4 v0 = *(const float4*)&g_Hi[(size_t)s0 * 128 + lane * 4];
        float4 v1 = *(const float4*)&g_Hi[(size_t)s1 * 128 + lane * 4];
        acc.x += n0 * v0.x + n1 * v1.x;
        acc.y += n0 * v0.y + n1 * v1.y;
        acc.z += n0 * v0.z + n1 * v1.z;
        acc.w += n0 * v0.w + n1 * v1.w;
    }
    if (e < end) {
        int s0 = g_src[e];
        float n0 = g_nrm_s[e];
        float4 v0 = *(const float4*)&g_Hi[(size_t)s0 * 128 + lane * 4];
        acc.x += n0 * v0.x; acc.y += n0 * v0.y; acc.z += n0 * v0.z; acc.w += n0 * v0.w;
    }
    float4 r = *(const float4*)&g_Hr[(size_t)n * 128 + lane * 4];
    float4 b = *(const float4*)&bias[lane * 4];
    float4 o;
    o.x = fmaxf(acc.x + r.x + b.x, 0.f);
    o.y = fmaxf(acc.y + r.y + b.y, 0.f);
    o.z = fmaxf(acc.z + r.z + b.z, 0.f);
    o.w = fmaxf(acc.w + r.w + b.w, 0.f);
    int g = batch[n];
    float* p = &g_pool[(size_t)g * 128 + lane * 4];
    atomicAdd(p + 0, o.x);
    atomicAdd(p + 1, o.y);
    atomicAdd(p + 2, o.z);
    atomicAdd(p + 3, o.w);
    if (lane == 0) atomicAdd(&g_pcnt[g], 1.f);
}

// ---------------- pool finalize + MLP ----------------------------------------
__global__ void k_mlp(const float* __restrict__ w1, const float* __restrict__ b1,
                      const float* __restrict__ w2, const float* __restrict__ b2,
                      float* __restrict__ out) {
    __shared__ float gx[128];
    __shared__ float hid[256];
    int g = blockIdx.x;
    int t = threadIdx.x;
    if (t < 128) {
        float c = fmaxf(g_pcnt[g], 1.f);
        gx[t] = g_pool[(size_t)g * 128 + t] / c;
    }
    __syncthreads();
    float acc = b1[t];
    #pragma unroll 8
    for (int k = 0; k < 128; k++) acc += gx[k] * w1[k * 256 + t];
    hid[t] = fmaxf(acc, 0.f);
    __syncthreads();
    int warp = t >> 5, lane = t & 31;
    if (warp < 2) {
        int c = warp;
        float s = 0.f;
        for (int k = lane; k < 256; k += 32) s += hid[k] * w2[k * 2 + c];
        #pragma unroll
        for (int d = 16; d > 0; d >>= 1) s += __shfl_xor_sync(0xFFFFFFFF, s, d);
        if (lane == 0) out[g * 2 + c] = s + b2[c];
    }
}

// ---------------- launch (fork-join: CSR build overlaps split+GEMM0) ----------
extern "C" void kernel_launch(void* const* d_in, const int* in_sizes, int n_in,
                              void* d_out, int out_size) {
    const float* x     = (const float*)d_in[0];
    const int*   ei    = (const int*)d_in[1];
    const float* ea    = (const float*)d_in[2];
    const int*   batch = (const int*)d_in[3];
    const float* w_init0 = (const float*)d_in[4];
    const float* w_root0 = (const float*)d_in[5];
    const float* b0      = (const float*)d_in[6];
    const float* w_init1 = (const float*)d_in[7];
    const float* w_root1 = (const float*)d_in[8];
    const float* b1      = (const float*)d_in[9];
    const float* mlp_w1  = (const float*)d_in[10];
    const float* mlp_b1  = (const float*)d_in[11];
    const float* mlp_w2  = (const float*)d_in[12];
    const float* mlp_b2  = (const float*)d_in[13];
    float* out = (float*)d_out;

    const int TB = 256;
    int nBlkN = (Nn + TB - 1) / TB;
    int nBlkE = (Ee + TB - 1) / TB;
    dim3 gg((Nn + 127) / 128, 2);

    cudaStream_t s2;
    cudaEvent_t evFork, evJoin;
    bool forked = (cudaStreamCreateWithFlags(&s2, cudaStreamNonBlocking) == cudaSuccess) &&
                  (cudaEventCreateWithFlags(&evFork, cudaEventDisableTiming) == cudaSuccess) &&
                  (cudaEventCreateWithFlags(&evJoin, cudaEventDisableTiming) == cudaSuccess);

    if (forked && cudaEventRecord(evFork, 0) == cudaSuccess &&
        cudaStreamWaitEvent(s2, evFork, 0) == cudaSuccess) {
        int nz = ((NG * HID > Nn ? NG * HID : Nn) + TB - 1) / TB;
        k_zero<<<nz, TB, 0, s2>>>();
        k_degcnt<<<nBlkE, TB, 0, s2>>>(ei, ea);
        k_scan1<<<NB_SCAN, 1024, 0, s2>>>();
        k_scan2<<<1, 1, 0, s2>>>();
        k_scan3<<<NB_SCAN, 1024, 0, s2>>>();
        k_scatter<<<nBlkE, TB, 0, s2>>>(ei, ea);
        cudaEventRecord(evJoin, s2);

        k_split_x<<<(Nn * 128 + TB - 1) / TB, TB>>>(x);
        k_wsplit<true><<<(256 * 256 + TB - 1) / TB, TB>>>(w_init0, w_root0);
        k_wsplit<false><<<(256 * 128 + TB - 1) / TB, TB>>>(w_init1, w_root1);
        k_mma<true><<<gg, 256>>>();

        cudaStreamWaitEvent(0, evJoin, 0);
    } else {
        int nz = ((NG * HID > Nn ? NG * HID : Nn) + TB - 1) / TB;
        k_zero<<<nz, TB>>>();
        k_degcnt<<<nBlkE, TB>>>(ei, ea);
        k_scan1<<<NB_SCAN, 1024>>>();
        k_scan2<<<1, 1>>>();
        k_scan3<<<NB_SCAN, 1024>>>();
        k_scatter<<<nBlkE, TB>>>(ei, ea);
        k_split_x<<<(Nn * 128 + TB - 1) / TB, TB>>>(x);
        k_wsplit<true><<<(256 * 256 + TB - 1) / TB, TB>>>(w_init0, w_root0);
        k_wsplit<false><<<(256 * 128 + TB - 1) / TB, TB>>>(w_init1, w_root1);
        k_mma<true><<<gg, 256>>>();
    }

    k_agg0<<<(Nn + 7) / 8, 256>>>(b0);
    k_mma<false><<<gg, 256>>>();
    k_agg1<<<(Nn + 7) / 8, 256>>>(b1, batch);
    k_mlp<<<NG, 256>>>(mlp_w1, mlp_b1, mlp_w2, mlp_b2, out);

    if (forked) {
        cudaStreamDestroy(s2);
        cudaEventDestroy(evFork);
        cudaEventDestroy(evJoin);
    }
}

// round 9
// speedup vs baseline: 2.6124x; 1.2195x over previous
#include <cuda_runtime.h>
#include <cuda_fp16.h>
#include <cstdint>

// Problem constants
#define Nn   100000
#define Ee   1600000
#define HID  128
#define NG   512
#define NB_SCAN 98        // ceil(100000/1024)

// ---------------- scratch (static device memory) -----------------------------
__device__ __align__(128) float g_Hi[(size_t)Nn * 128];
__device__ __align__(128) float g_Hr[(size_t)Nn * 128];
__device__ __align__(128) __half g_A0[(size_t)Nn * 256];
__device__ __align__(128) __half g_A1[(size_t)Nn * 128];
__device__ __align__(128) __half g_B0[256 * 256];
__device__ __align__(128) __half g_B1[256 * 128];
__device__ float g_deg[Nn];
__device__ int   g_cnt[Nn];
__device__ int   g_off[Nn];
__device__ int   g_cur[Nn];
__device__ int   g_src[Ee];
__device__ float g_nrm_s[Ee];
__device__ int   g_psum[NB_SCAN];
__device__ int   g_boff[NB_SCAN];
__device__ float g_pool[NG * HID];
__device__ float g_pcnt[NG];

// ---------------- PTX helpers (base sm_100 features only) --------------------
__device__ __forceinline__ uint32_t s2u(const void* p) {
    uint32_t a;
    asm("{ .reg .u64 t; cvta.to.shared.u64 t, %1; cvt.u32.u64 %0, t; }" : "=r"(a) : "l"(p));
    return a;
}
__device__ __forceinline__ void ldm_x4(uint32_t& r0, uint32_t& r1, uint32_t& r2, uint32_t& r3,
                                       uint32_t addr) {
    asm volatile("ldmatrix.sync.aligned.m8n8.x4.shared.b16 {%0,%1,%2,%3}, [%4];"
                 : "=r"(r0), "=r"(r1), "=r"(r2), "=r"(r3) : "r"(addr));
}
__device__ __forceinline__ void ldm_x2(uint32_t& r0, uint32_t& r1, uint32_t addr) {
    asm volatile("ldmatrix.sync.aligned.m8n8.x2.shared.b16 {%0,%1}, [%2];"
                 : "=r"(r0), "=r"(r1) : "r"(addr));
}
__device__ __forceinline__ void mma_f16(float* c, const uint32_t* a, const uint32_t* b) {
    asm volatile(
        "mma.sync.aligned.m16n8k16.row.col.f32.f16.f16.f32 "
        "{%0,%1,%2,%3}, {%4,%5,%6,%7}, {%8,%9}, {%0,%1,%2,%3};"
        : "+f"(c[0]), "+f"(c[1]), "+f"(c[2]), "+f"(c[3])
        : "r"(a[0]), "r"(a[1]), "r"(a[2]), "r"(a[3]), "r"(b[0]), "r"(b[1]));
}
__device__ __forceinline__ void cpa16(uint32_t saddr, const void* gaddr) {
    asm volatile("cp.async.cg.shared.global [%0], [%1], 16;" :: "r"(saddr), "l"(gaddr));
}
__device__ __forceinline__ void cpa_commit(void) {
    asm volatile("cp.async.commit_group;" ::: "memory");
}
template <int N>
__device__ __forceinline__ void cpa_wait(void) {
    asm volatile("cp.async.wait_group %0;" :: "n"(N) : "memory");
}

// ---------------- fused zero + CSR build kernels ------------------------------
__global__ void k_zero(void) {
    int i = blockIdx.x * blockDim.x + threadIdx.x;
    if (i < Nn) { g_deg[i] = 0.f; g_cnt[i] = 0; }
    if (i < NG * HID) g_pool[i] = 0.f;
    if (i < NG) g_pcnt[i] = 0.f;
}
__global__ void k_degcnt(const int* __restrict__ ei, const float* __restrict__ w) {
    int e = blockIdx.x * blockDim.x + threadIdx.x;
    if (e >= Ee) return;
    int col = ei[Ee + e];
    atomicAdd(&g_deg[col], w[e]);
    atomicAdd(&g_cnt[col], 1);
}
// scan1 with fused dinv
__global__ void k_scan1(void) {
    __shared__ int s[1024];
    int t = threadIdx.x;
    int i = blockIdx.x * 1024 + t;
    if (i < Nn) {
        float d = g_deg[i];
        g_deg[i] = (d > 0.f) ? rsqrtf(d) : 0.f;
    }
    s[t] = (i < Nn) ? g_cnt[i] : 0;
    __syncthreads();
    for (int d = 512; d > 0; d >>= 1) {
        if (t < d) s[t] += s[t + d];
        __syncthreads();
    }
    if (t == 0) g_psum[blockIdx.x] = s[0];
}
// parallel exclusive scan of 98 block sums (1 block, 128 threads)
__global__ void k_scan2(void) {
    __shared__ int warpsum[4];
    int t = threadIdx.x;
    int lane = t & 31, w = t >> 5;
    int v = (t < NB_SCAN) ? g_psum[t] : 0;
    int inc = v;
    #pragma unroll
    for (int d = 1; d < 32; d <<= 1) {
        int o = __shfl_up_sync(0xFFFFFFFF, inc, d);
        if (lane >= d) inc += o;
    }
    if (lane == 31) warpsum[w] = inc;
    __syncthreads();
    int base = 0;
    #pragma unroll
    for (int k = 0; k < 4; k++) if (k < w) base += warpsum[k];
    if (t < NB_SCAN) g_boff[t] = base + inc - v;   // exclusive
}
__global__ void k_scan3(void) {
    __shared__ int s[1024];
    int t = threadIdx.x;
    int i = blockIdx.x * 1024 + t;
    int v = (i < Nn) ? g_cnt[i] : 0;
    s[t] = v;
    __syncthreads();
    for (int d = 1; d < 1024; d <<= 1) {
        int add = (t >= d) ? s[t - d] : 0;
        __syncthreads();
        s[t] += add;
        __syncthreads();
    }
    if (i < Nn) {
        int excl = g_boff[blockIdx.x] + s[t] - v;
        g_off[i] = excl;
        g_cur[i] = excl;
    }
}
__global__ void k_scatter(const int* __restrict__ ei, const float* __restrict__ w) {
    int e = blockIdx.x * blockDim.x + threadIdx.x;
    if (e >= Ee) return;
    int row = ei[e];
    int col = ei[Ee + e];
    int pos = atomicAdd(&g_cur[col], 1);
    g_src[pos] = row;
    g_nrm_s[pos] = g_deg[row] * w[e] * g_deg[col];
}

// ---------------- fp16 conversion preps --------------------------------------
__global__ void k_split_x(const float* __restrict__ x) {
    size_t i = (size_t)blockIdx.x * blockDim.x + threadIdx.x;
    if (i >= (size_t)Nn * 64) return;   // 4 elems each (256 cols)
    float4 v = ((const float4*)x)[i];
    __half2 a = __halves2half2(__float2half(v.x), __float2half(v.y));
    __half2 b = __halves2half2(__float2half(v.z), __float2half(v.w));
    ((__half2*)g_A0)[i * 2 + 0] = a;
    ((__half2*)g_A0)[i * 2 + 1] = b;
}
template <bool FIRST>
__global__ void k_wsplit(const float* __restrict__ wi, const float* __restrict__ wr) {
    const int K = FIRST ? 256 : 128;
    int idx = blockIdx.x * blockDim.x + threadIdx.x;
    if (idx >= 256 * K) return;
    int n = idx / K, k = idx % K;
    float w = (n < 128) ? wi[k * 128 + n] : wr[k * 128 + (n - 128)];
    if (FIRST) g_B0[idx] = __float2half(w);
    else       g_B1[idx] = __float2half(w);
}

// ---------------- pipelined mma.sync GEMM (single-phase fp16) ----------------
#define SROW 40   // smem row stride in halves (32 data + 8 pad) -> 80 bytes
template <bool FIRST>
__global__ void __launch_bounds__(256, 2) k_mma(void) {
    constexpr int K  = FIRST ? 256 : 128;
    constexpr int NC = K / 32;
    __shared__ __align__(16) __half sA[2][128 * SROW];
    __shared__ __align__(16) __half sB[2][128 * SROW];

    const __half* Aw = FIRST ? g_A0 : g_A1;
    const __half* Bw = FIRST ? g_B0 : g_B1;

    int tid = threadIdx.x, lane = tid & 31, wid = tid >> 5;
    int warp_m = wid >> 2;
    int warp_n = wid & 3;
    int rowBase = blockIdx.x * 128;
    float* Hout = (blockIdx.y == 0) ? g_Hi : g_Hr;
    int nBase = blockIdx.y * 128;

    auto issue_chunk = [&](int c, int buf) {
        int k0 = c * 32;
        #pragma unroll
        for (int j = tid; j < 1024; j += 256) {
            int isB = j >= 512;
            int i = j & 511;
            int row = i >> 2, q = i & 3;
            const __half* src;
            if (!isB) {
                int rg = rowBase + row;
                if (rg >= Nn) rg = Nn - 1;
                src = &Aw[(size_t)rg * K + k0 + q * 8];
            } else {
                src = &Bw[(size_t)(nBase + row) * K + k0 + q * 8];
            }
            uint32_t dst = s2u(&(isB ? sB : sA)[buf][row * SROW + q * 8]);
            cpa16(dst, src);
        }
        cpa_commit();
    };

    float acc[4][4][4] = {};

    issue_chunk(0, 0);
    for (int c = 0; c < NC; ++c) {
        int buf = c & 1;
        cpa_wait<0>();
        __syncthreads();
        if (c + 1 < NC) issue_chunk(c + 1, buf ^ 1);
        uint32_t aB = s2u(&sA[buf][0]), bB = s2u(&sB[buf][0]);
        #pragma unroll
        for (int kk = 0; kk < 2; kk++) {
            int k16 = kk * 16;
            uint32_t a[4][4];
            #pragma unroll
            for (int mt = 0; mt < 4; mt++) {
                int row = warp_m * 64 + mt * 16 + (lane & 15);
                uint32_t addr = aB + (uint32_t)(row * SROW + k16 + (lane >> 4) * 8) * 2;
                ldm_x4(a[mt][0], a[mt][1], a[mt][2], a[mt][3], addr);
            }
            uint32_t b[4][2];
            #pragma unroll
            for (int nt = 0; nt < 4; nt++) {
                int row = warp_n * 32 + nt * 8 + (lane & 7);
                uint32_t addr = bB + (uint32_t)(row * SROW + k16 + ((lane >> 3) & 1) * 8) * 2;
                ldm_x2(b[nt][0], b[nt][1], addr);
            }
            #pragma unroll
            for (int mt = 0; mt < 4; mt++)
                #pragma unroll
                for (int nt = 0; nt < 4; nt++)
                    mma_f16(acc[mt][nt], a[mt], b[nt]);
        }
        __syncthreads();
    }

    #pragma unroll
    for (int mt = 0; mt < 4; mt++) {
        int m0 = rowBase + warp_m * 64 + mt * 16 + (lane >> 2);
        int m1 = m0 + 8;
        #pragma unroll
        for (int nt = 0; nt < 4; nt++) {
            int col = warp_n * 32 + nt * 8 + (lane & 3) * 2;
            if (m0 < Nn) {
                float2 v = make_float2(acc[mt][nt][0], acc[mt][nt][1]);
                *(float2*)&Hout[(size_t)m0 * 128 + col] = v;
            }
            if (m1 < Nn) {
                float2 v = make_float2(acc[mt][nt][2], acc[mt][nt][3]);
                *(float2*)&Hout[(size_t)m1 * 128 + col] = v;
            }
        }
    }
}

// ---------------- Aggregation: warp per node ---------------------------------
__global__ void k_agg0(const float* __restrict__ bias) {
    int warp = threadIdx.x >> 5;
    int lane = threadIdx.x & 31;
    int n = blockIdx.x * 8 + warp;
    if (n >= Nn) return;
    int e = g_off[n];
    int end = e + g_cnt[n];
    float4 acc = make_float4(0.f, 0.f, 0.f, 0.f);
    for (; e + 1 < end; e += 2) {
        int s0 = g_src[e], s1 = g_src[e + 1];
        float n0 = g_nrm_s[e], n1 = g_nrm_s[e + 1];
        float4 v0 = *(const float4*)&g_Hi[(size_t)s0 * 128 + lane * 4];
        float4 v1 = *(const float4*)&g_Hi[(size_t)s1 * 128 + lane * 4];
        acc.x += n0 * v0.x + n1 * v1.x;
        acc.y += n0 * v0.y + n1 * v1.y;
        acc.z += n0 * v0.z + n1 * v1.z;
        acc.w += n0 * v0.w + n1 * v1.w;
    }
    if (e < end) {
        int s0 = g_src[e];
        float n0 = g_nrm_s[e];
        float4 v0 = *(const float4*)&g_Hi[(size_t)s0 * 128 + lane * 4];
        acc.x += n0 * v0.x; acc.y += n0 * v0.y; acc.z += n0 * v0.z; acc.w += n0 * v0.w;
    }
    float4 r = *(const float4*)&g_Hr[(size_t)n * 128 + lane * 4];
    float4 b = *(const float4*)&bias[lane * 4];
    float o0 = fmaxf(acc.x + r.x + b.x, 0.f);
    float o1 = fmaxf(acc.y + r.y + b.y, 0.f);
    float o2 = fmaxf(acc.z + r.z + b.z, 0.f);
    float o3 = fmaxf(acc.w + r.w + b.w, 0.f);
    __half2* ph = (__half2*)&g_A1[(size_t)n * 128 + lane * 4];
    ph[0] = __halves2half2(__float2half(o0), __float2half(o1));
    ph[1] = __halves2half2(__float2half(o2), __float2half(o3));
}

__global__ void k_agg1(const float* __restrict__ bias, const int* __restrict__ batch) {
    int warp = threadIdx.x >> 5;
    int lane = threadIdx.x & 31;
    int n = blockIdx.x * 8 + warp;
    if (n >= Nn) return;
    int e = g_off[n];
    int end = e + g_cnt[n];
    float4 acc = make_float4(0.f, 0.f, 0.f, 0.f);
    for (; e + 1 < end; e += 2) {
        int s0 = g_src[e], s1 = g_src[e + 1];
        float n0 = g_nrm_s[e], n1 = g_nrm_s[e + 1];
        float4 v0 = *(const float4*)&g_Hi[(size_t)s0 * 128 + lane * 4];
        float4 v1 = *(const float4*)&g_Hi[(size_t)s1 * 128 + lane * 4];
        acc.x += n0 * v0.x + n1 * v1.x;
        acc.y += n0 * v0.y + n1 * v1.y;
        acc.z += n0 * v0.z + n1 * v1.z;
        acc.w += n0 * v0.w + n1 * v1.w;
    }
    if (e < end) {
        int s0 = g_src[e];
        float n0 = g_nrm_s[e];
        float4 v0 = *(const float4*)&g_Hi[(size_t)s0 * 128 + lane * 4];
        acc.x += n0 * v0.x; acc.y += n0 * v0.y; acc.z += n0 * v0.z; acc.w += n0 * v0.w;
    }
    float4 r = *(const float4*)&g_Hr[(size_t)n * 128 + lane * 4];
    float4 b = *(const float4*)&bias[lane * 4];
    float4 o;
    o.x = fmaxf(acc.x + r.x + b.x, 0.f);
    o.y = fmaxf(acc.y + r.y + b.y, 0.f);
    o.z = fmaxf(acc.z + r.z + b.z, 0.f);
    o.w = fmaxf(acc.w + r.w + b.w, 0.f);
    int g = batch[n];
    float* p = &g_pool[(size_t)g * 128 + lane * 4];
    atomicAdd(p + 0, o.x);
    atomicAdd(p + 1, o.y);
    atomicAdd(p + 2, o.z);
    atomicAdd(p + 3, o.w);
    if (lane == 0) atomicAdd(&g_pcnt[g], 1.f);
}

// ---------------- pool finalize + MLP ----------------------------------------
__global__ void k_mlp(const float* __restrict__ w1, const float* __restrict__ b1,
                      const float* __restrict__ w2, const float* __restrict__ b2,
                      float* __restrict__ out) {
    __shared__ float gx[128];
    __shared__ float hid[256];
    int g = blockIdx.x;
    int t = threadIdx.x;
    if (t < 128) {
        float c = fmaxf(g_pcnt[g], 1.f);
        gx[t] = g_pool[(size_t)g * 128 + t] / c;
    }
    __syncthreads();
    float acc = b1[t];
    #pragma unroll 8
    for (int k = 0; k < 128; k++) acc += gx[k] * w1[k * 256 + t];
    hid[t] = fmaxf(acc, 0.f);
    __syncthreads();
    int warp = t >> 5, lane = t & 31;
    if (warp < 2) {
        int c = warp;
        float s = 0.f;
        for (int k = lane; k < 256; k += 32) s += hid[k] * w2[k * 2 + c];
        #pragma unroll
        for (int d = 16; d > 0; d >>= 1) s += __shfl_xor_sync(0xFFFFFFFF, s, d);
        if (lane == 0) out[g * 2 + c] = s + b2[c];
    }
}

// ---------------- launch (fork-join: CSR build overlaps split+GEMM0) ----------
extern "C" void kernel_launch(void* const* d_in, const int* in_sizes, int n_in,
                              void* d_out, int out_size) {
    const float* x     = (const float*)d_in[0];
    const int*   ei    = (const int*)d_in[1];
    const float* ea    = (const float*)d_in[2];
    const int*   batch = (const int*)d_in[3];
    const float* w_init0 = (const float*)d_in[4];
    const float* w_root0 = (const float*)d_in[5];
    const float* b0      = (const float*)d_in[6];
    const float* w_init1 = (const float*)d_in[7];
    const float* w_root1 = (const float*)d_in[8];
    const float* b1      = (const float*)d_in[9];
    const float* mlp_w1  = (const float*)d_in[10];
    const float* mlp_b1  = (const float*)d_in[11];
    const float* mlp_w2  = (const float*)d_in[12];
    const float* mlp_b2  = (const float*)d_in[13];
    float* out = (float*)d_out;

    const int TB = 256;
    int nBlkE = (Ee + TB - 1) / TB;
    dim3 gg((Nn + 127) / 128, 2);

    cudaStream_t s2;
    cudaEvent_t evFork, evJoin;
    bool forked = (cudaStreamCreateWithFlags(&s2, cudaStreamNonBlocking) == cudaSuccess) &&
                  (cudaEventCreateWithFlags(&evFork, cudaEventDisableTiming) == cudaSuccess) &&
                  (cudaEventCreateWithFlags(&evJoin, cudaEventDisableTiming) == cudaSuccess);

    if (forked && cudaEventRecord(evFork, 0) == cudaSuccess &&
        cudaStreamWaitEvent(s2, evFork, 0) == cudaSuccess) {
        int nz = ((NG * HID > Nn ? NG * HID : Nn) + TB - 1) / TB;
        k_zero<<<nz, TB, 0, s2>>>();
        k_degcnt<<<nBlkE, TB, 0, s2>>>(ei, ea);
        k_scan1<<<NB_SCAN, 1024, 0, s2>>>();
        k_scan2<<<1, 128, 0, s2>>>();
        k_scan3<<<NB_SCAN, 1024, 0, s2>>>();
        k_scatter<<<nBlkE, TB, 0, s2>>>(ei, ea);
        cudaEventRecord(evJoin, s2);

        k_split_x<<<(Nn * 64 + TB - 1) / TB, TB>>>(x);
        k_wsplit<true><<<(256 * 256 + TB - 1) / TB, TB>>>(w_init0, w_root0);
        k_wsplit<false><<<(256 * 128 + TB - 1) / TB, TB>>>(w_init1, w_root1);
        k_mma<true><<<gg, 256>>>();

        cudaStreamWaitEvent(0, evJoin, 0);
    } else {
        int nz = ((NG * HID > Nn ? NG * HID : Nn) + TB - 1) / TB;
        k_zero<<<nz, TB>>>();
        k_degcnt<<<nBlkE, TB>>>(ei, ea);
        k_scan1<<<NB_SCAN, 1024>>>();
        k_scan2<<<1, 128>>>();
        k_scan3<<<NB_SCAN, 1024>>>();
        k_scatter<<<nBlkE, TB>>>(ei, ea);
        k_split_x<<<(Nn * 64 + TB - 1) / TB, TB>>>(x);
        k_wsplit<true><<<(256 * 256 + TB - 1) / TB, TB>>>(w_init0, w_root0);
        k_wsplit<false><<<(256 * 128 + TB - 1) / TB, TB>>>(w_init1, w_root1);
        k_mma<true><<<gg, 256>>>();
    }

    k_agg0<<<(Nn + 7) / 8, 256>>>(b0);
    k_mma<false><<<gg, 256>>>();
    k_agg1<<<(Nn + 7) / 8, 256>>>(b1, batch);
    k_mlp<<<NG, 256>>>(mlp_w1, mlp_b1, mlp_w2, mlp_b2, out);

    if (forked) {
        cudaStreamDestroy(s2);
        cudaEventDestroy(evFork);
        cudaEventDestroy(evJoin);
    }
}

// round 11
// speedup vs baseline: 3.0322x; 1.1607x over previous
#include <cuda_runtime.h>
#include <cuda_fp16.h>
#include <cstdint>

// Problem constants
#define Nn   100000
#define Ee   1600000
#define HID  128
#define NG   512
#define NB_SCAN 98        // ceil(100000/1024)

// ---------------- scratch (static device memory) -----------------------------
__device__ __align__(128) __half g_Hi[(size_t)Nn * 128];   // GEMM init-half out (fp16)
__device__ __align__(128) __half g_Hr[(size_t)Nn * 128];   // GEMM root-half out (fp16)
__device__ __align__(128) __half g_A0[(size_t)Nn * 256];
__device__ __align__(128) __half g_A1[(size_t)Nn * 128];
__device__ __align__(128) __half g_B0[256 * 256];
__device__ __align__(128) __half g_B1[256 * 128];
__device__ float g_deg[Nn];
__device__ int   g_cnt[Nn];
__device__ int   g_off[Nn];
__device__ int   g_cur[Nn];
__device__ int   g_src[Ee];
__device__ float g_nrm_s[Ee];
__device__ int   g_psum[NB_SCAN];
__device__ int   g_boff[NB_SCAN];
__device__ float g_pool[NG * HID];
__device__ float g_pcnt[NG];

// ---------------- PTX helpers (base sm_100 features only) --------------------
__device__ __forceinline__ uint32_t s2u(const void* p) {
    uint32_t a;
    asm("{ .reg .u64 t; cvta.to.shared.u64 t, %1; cvt.u32.u64 %0, t; }" : "=r"(a) : "l"(p));
    return a;
}
__device__ __forceinline__ void ldm_x4(uint32_t& r0, uint32_t& r1, uint32_t& r2, uint32_t& r3,
                                       uint32_t addr) {
    asm volatile("ldmatrix.sync.aligned.m8n8.x4.shared.b16 {%0,%1,%2,%3}, [%4];"
                 : "=r"(r0), "=r"(r1), "=r"(r2), "=r"(r3) : "r"(addr));
}
__device__ __forceinline__ void ldm_x2(uint32_t& r0, uint32_t& r1, uint32_t addr) {
    asm volatile("ldmatrix.sync.aligned.m8n8.x2.shared.b16 {%0,%1}, [%2];"
                 : "=r"(r0), "=r"(r1) : "r"(addr));
}
__device__ __forceinline__ void mma_f16(float* c, const uint32_t* a, const uint32_t* b) {
    asm volatile(
        "mma.sync.aligned.m16n8k16.row.col.f32.f16.f16.f32 "
        "{%0,%1,%2,%3}, {%4,%5,%6,%7}, {%8,%9}, {%0,%1,%2,%3};"
        : "+f"(c[0]), "+f"(c[1]), "+f"(c[2]), "+f"(c[3])
        : "r"(a[0]), "r"(a[1]), "r"(a[2]), "r"(a[3]), "r"(b[0]), "r"(b[1]));
}
__device__ __forceinline__ void cpa16(uint32_t saddr, const void* gaddr) {
    asm volatile("cp.async.cg.shared.global [%0], [%1], 16;" :: "r"(saddr), "l"(gaddr));
}
__device__ __forceinline__ void cpa_commit(void) {
    asm volatile("cp.async.commit_group;" ::: "memory");
}
template <int N>
__device__ __forceinline__ void cpa_wait(void) {
    asm volatile("cp.async.wait_group %0;" :: "n"(N) : "memory");
}

// ---------------- fused zero + CSR build kernels ------------------------------
__global__ void k_zero(void) {
    int i = blockIdx.x * blockDim.x + threadIdx.x;
    if (i < Nn) { g_deg[i] = 0.f; g_cnt[i] = 0; }
    if (i < NG * HID) g_pool[i] = 0.f;
    if (i < NG) g_pcnt[i] = 0.f;
}
__global__ void k_degcnt(const int* __restrict__ ei, const float* __restrict__ w) {
    int e = blockIdx.x * blockDim.x + threadIdx.x;
    if (e >= Ee) return;
    int col = ei[Ee + e];
    atomicAdd(&g_deg[col], w[e]);
    atomicAdd(&g_cnt[col], 1);
}
__global__ void k_scan1(void) {
    __shared__ int s[1024];
    int t = threadIdx.x;
    int i = blockIdx.x * 1024 + t;
    if (i < Nn) {
        float d = g_deg[i];
        g_deg[i] = (d > 0.f) ? rsqrtf(d) : 0.f;
    }
    s[t] = (i < Nn) ? g_cnt[i] : 0;
    __syncthreads();
    for (int d = 512; d > 0; d >>= 1) {
        if (t < d) s[t] += s[t + d];
        __syncthreads();
    }
    if (t == 0) g_psum[blockIdx.x] = s[0];
}
__global__ void k_scan2(void) {
    __shared__ int warpsum[4];
    int t = threadIdx.x;
    int lane = t & 31, w = t >> 5;
    int v = (t < NB_SCAN) ? g_psum[t] : 0;
    int inc = v;
    #pragma unroll
    for (int d = 1; d < 32; d <<= 1) {
        int o = __shfl_up_sync(0xFFFFFFFF, inc, d);
        if (lane >= d) inc += o;
    }
    if (lane == 31) warpsum[w] = inc;
    __syncthreads();
    int base = 0;
    #pragma unroll
    for (int k = 0; k < 4; k++) if (k < w) base += warpsum[k];
    if (t < NB_SCAN) g_boff[t] = base + inc - v;
}
__global__ void k_scan3(void) {
    __shared__ int s[1024];
    int t = threadIdx.x;
    int i = blockIdx.x * 1024 + t;
    int v = (i < Nn) ? g_cnt[i] : 0;
    s[t] = v;
    __syncthreads();
    for (int d = 1; d < 1024; d <<= 1) {
        int add = (t >= d) ? s[t - d] : 0;
        __syncthreads();
        s[t] += add;
        __syncthreads();
    }
    if (i < Nn) {
        int excl = g_boff[blockIdx.x] + s[t] - v;
        g_off[i] = excl;
        g_cur[i] = excl;
    }
}
__global__ void k_scatter(const int* __restrict__ ei, const float* __restrict__ w) {
    int e = blockIdx.x * blockDim.x + threadIdx.x;
    if (e >= Ee) return;
    int row = ei[e];
    int col = ei[Ee + e];
    int pos = atomicAdd(&g_cur[col], 1);
    g_src[pos] = row;
    g_nrm_s[pos] = g_deg[row] * w[e] * g_deg[col];
}

// ---------------- fp16 conversion preps --------------------------------------
__global__ void k_split_x(const float* __restrict__ x) {
    size_t i = (size_t)blockIdx.x * blockDim.x + threadIdx.x;
    if (i >= (size_t)Nn * 64) return;
    float4 v = ((const float4*)x)[i];
    __half2 a = __halves2half2(__float2half(v.x), __float2half(v.y));
    __half2 b = __halves2half2(__float2half(v.z), __float2half(v.w));
    ((__half2*)g_A0)[i * 2 + 0] = a;
    ((__half2*)g_A0)[i * 2 + 1] = b;
}
template <bool FIRST>
__global__ void k_wsplit(const float* __restrict__ wi, const float* __restrict__ wr) {
    const int K = FIRST ? 256 : 128;
    int idx = blockIdx.x * blockDim.x + threadIdx.x;
    if (idx >= 256 * K) return;
    int n = idx / K, k = idx % K;
    float w = (n < 128) ? wi[k * 128 + n] : wr[k * 128 + (n - 128)];
    if (FIRST) g_B0[idx] = __float2half(w);
    else       g_B1[idx] = __float2half(w);
}

// ---------------- pipelined mma.sync GEMM (fp16 out) -------------------------
#define SROW 40
template <bool FIRST>
__global__ void __launch_bounds__(256, 2) k_mma(void) {
    constexpr int K  = FIRST ? 256 : 128;
    constexpr int NC = K / 32;
    __shared__ __align__(16) __half sA[2][128 * SROW];
    __shared__ __align__(16) __half sB[2][128 * SROW];

    const __half* Aw = FIRST ? g_A0 : g_A1;
    const __half* Bw = FIRST ? g_B0 : g_B1;

    int tid = threadIdx.x, lane = tid & 31, wid = tid >> 5;
    int warp_m = wid >> 2;
    int warp_n = wid & 3;
    int rowBase = blockIdx.x * 128;
    __half* Hout = (blockIdx.y == 0) ? g_Hi : g_Hr;
    int nBase = blockIdx.y * 128;

    auto issue_chunk = [&](int c, int buf) {
        int k0 = c * 32;
        #pragma unroll
        for (int j = tid; j < 1024; j += 256) {
            int isB = j >= 512;
            int i = j & 511;
            int row = i >> 2, q = i & 3;
            const __half* src;
            if (!isB) {
                int rg = rowBase + row;
                if (rg >= Nn) rg = Nn - 1;
                src = &Aw[(size_t)rg * K + k0 + q * 8];
            } else {
                src = &Bw[(size_t)(nBase + row) * K + k0 + q * 8];
            }
            uint32_t dst = s2u(&(isB ? sB : sA)[buf][row * SROW + q * 8]);
            cpa16(dst, src);
        }
        cpa_commit();
    };

    float acc[4][4][4] = {};

    issue_chunk(0, 0);
    for (int c = 0; c < NC; ++c) {
        int buf = c & 1;
        cpa_wait<0>();
        __syncthreads();
        if (c + 1 < NC) issue_chunk(c + 1, buf ^ 1);
        uint32_t aB = s2u(&sA[buf][0]), bB = s2u(&sB[buf][0]);
        #pragma unroll
        for (int kk = 0; kk < 2; kk++) {
            int k16 = kk * 16;
            uint32_t a[4][4];
            #pragma unroll
            for (int mt = 0; mt < 4; mt++) {
                int row = warp_m * 64 + mt * 16 + (lane & 15);
                uint32_t addr = aB + (uint32_t)(row * SROW + k16 + (lane >> 4) * 8) * 2;
                ldm_x4(a[mt][0], a[mt][1], a[mt][2], a[mt][3], addr);
            }
            uint32_t b[4][2];
            #pragma unroll
            for (int nt = 0; nt < 4; nt++) {
                int row = warp_n * 32 + nt * 8 + (lane & 7);
                uint32_t addr = bB + (uint32_t)(row * SROW + k16 + ((lane >> 3) & 1) * 8) * 2;
                ldm_x2(b[nt][0], b[nt][1], addr);
            }
            #pragma unroll
            for (int mt = 0; mt < 4; mt++)
                #pragma unroll
                for (int nt = 0; nt < 4; nt++)
                    mma_f16(acc[mt][nt], a[mt], b[nt]);
        }
        __syncthreads();
    }

    // epilogue: fp16 output (half2 stores)
    #pragma unroll
    for (int mt = 0; mt < 4; mt++) {
        int m0 = rowBase + warp_m * 64 + mt * 16 + (lane >> 2);
        int m1 = m0 + 8;
        #pragma unroll
        for (int nt = 0; nt < 4; nt++) {
            int col = warp_n * 32 + nt * 8 + (lane & 3) * 2;
            if (m0 < Nn) {
                *(__half2*)&Hout[(size_t)m0 * 128 + col] =
                    __halves2half2(__float2half(acc[mt][nt][0]), __float2half(acc[mt][nt][1]));
            }
            if (m1 < Nn) {
                *(__half2*)&Hout[(size_t)m1 * 128 + col] =
                    __halves2half2(__float2half(acc[mt][nt][2]), __float2half(acc[mt][nt][3]));
            }
        }
    }
}

// ---------------- Aggregation: warp per node, fp16 gathers -------------------
__device__ __forceinline__ void gather_add(float4& acc, const __half* rowp, float nm) {
    uint2 u = *(const uint2*)rowp;                 // 4 halves = 8 bytes
    float2 f0 = __half22float2(*(__half2*)&u.x);
    float2 f1 = __half22float2(*(__half2*)&u.y);
    acc.x += nm * f0.x; acc.y += nm * f0.y;
    acc.z += nm * f1.x; acc.w += nm * f1.y;
}

__global__ void k_agg0(const float* __restrict__ bias) {
    int warp = threadIdx.x >> 5;
    int lane = threadIdx.x & 31;
    int n = blockIdx.x * 8 + warp;
    if (n >= Nn) return;
    int e = g_off[n];
    int end = e + g_cnt[n];
    float4 acc = make_float4(0.f, 0.f, 0.f, 0.f);
    for (; e + 1 < end; e += 2) {
        int s0 = g_src[e], s1 = g_src[e + 1];
        float n0 = g_nrm_s[e], n1 = g_nrm_s[e + 1];
        gather_add(acc, &g_Hi[(size_t)s0 * 128 + lane * 4], n0);
        gather_add(acc, &g_Hi[(size_t)s1 * 128 + lane * 4], n1);
    }
    if (e < end) {
        gather_add(acc, &g_Hi[(size_t)g_src[e] * 128 + lane * 4], g_nrm_s[e]);
    }
    float4 r;
    {
        uint2 u = *(const uint2*)&g_Hr[(size_t)n * 128 + lane * 4];
        float2 f0 = __half22float2(*(__half2*)&u.x);
        float2 f1 = __half22float2(*(__half2*)&u.y);
        r = make_float4(f0.x, f0.y, f1.x, f1.y);
    }
    float4 b = *(const float4*)&bias[lane * 4];
    float o0 = fmaxf(acc.x + r.x + b.x, 0.f);
    float o1 = fmaxf(acc.y + r.y + b.y, 0.f);
    float o2 = fmaxf(acc.z + r.z + b.z, 0.f);
    float o3 = fmaxf(acc.w + r.w + b.w, 0.f);
    __half2* ph = (__half2*)&g_A1[(size_t)n * 128 + lane * 4];
    ph[0] = __halves2half2(__float2half(o0), __float2half(o1));
    ph[1] = __halves2half2(__float2half(o2), __float2half(o3));
}

__global__ void k_agg1(const float* __restrict__ bias, const int* __restrict__ batch) {
    int warp = threadIdx.x >> 5;
    int lane = threadIdx.x & 31;
    int n = blockIdx.x * 8 + warp;
    if (n >= Nn) return;
    int e = g_off[n];
    int end = e + g_cnt[n];
    float4 acc = make_float4(0.f, 0.f, 0.f, 0.f);
    for (; e + 1 < end; e += 2) {
        int s0 = g_src[e], s1 = g_src[e + 1];
        float n0 = g_nrm_s[e], n1 = g_nrm_s[e + 1];
        gather_add(acc, &g_Hi[(size_t)s0 * 128 + lane * 4], n0);
        gather_add(acc, &g_Hi[(size_t)s1 * 128 + lane * 4], n1);
    }
    if (e < end) {
        gather_add(acc, &g_Hi[(size_t)g_src[e] * 128 + lane * 4], g_nrm_s[e]);
    }
    float4 r;
    {
        uint2 u = *(const uint2*)&g_Hr[(size_t)n * 128 + lane * 4];
        float2 f0 = __half22float2(*(__half2*)&u.x);
        float2 f1 = __half22float2(*(__half2*)&u.y);
        r = make_float4(f0.x, f0.y, f1.x, f1.y);
    }
    float4 b = *(const float4*)&bias[lane * 4];
    float4 o;
    o.x = fmaxf(acc.x + r.x + b.x, 0.f);
    o.y = fmaxf(acc.y + r.y + b.y, 0.f);
    o.z = fmaxf(acc.z + r.z + b.z, 0.f);
    o.w = fmaxf(acc.w + r.w + b.w, 0.f);
    int g = batch[n];
    float* p = &g_pool[(size_t)g * 128 + lane * 4];
    atomicAdd(p + 0, o.x);
    atomicAdd(p + 1, o.y);
    atomicAdd(p + 2, o.z);
    atomicAdd(p + 3, o.w);
    if (lane == 0) atomicAdd(&g_pcnt[g], 1.f);
}

// ---------------- pool finalize + MLP ----------------------------------------
__global__ void k_mlp(const float* __restrict__ w1, const float* __restrict__ b1,
                      const float* __restrict__ w2, const float* __restrict__ b2,
                      float* __restrict__ out) {
    __shared__ float gx[128];
    __shared__ float hid[256];
    int g = blockIdx.x;
    int t = threadIdx.x;
    if (t < 128) {
        float c = fmaxf(g_pcnt[g], 1.f);
        gx[t] = g_pool[(size_t)g * 128 + t] / c;
    }
    __syncthreads();
    float acc = b1[t];
    #pragma unroll 8
    for (int k = 0; k < 128; k++) acc += gx[k] * w1[k * 256 + t];
    hid[t] = fmaxf(acc, 0.f);
    __syncthreads();
    int warp = t >> 5, lane = t & 31;
    if (warp < 2) {
        int c = warp;
        float s = 0.f;
        for (int k = lane; k < 256; k += 32) s += hid[k] * w2[k * 2 + c];
        #pragma unroll
        for (int d = 16; d > 0; d >>= 1) s += __shfl_xor_sync(0xFFFFFFFF, s, d);
        if (lane == 0) out[g * 2 + c] = s + b2[c];
    }
}

// ---------------- launch (fork-join: CSR build overlaps split+GEMM0) ----------
extern "C" void kernel_launch(void* const* d_in, const int* in_sizes, int n_in,
                              void* d_out, int out_size) {
    const float* x     = (const float*)d_in[0];
    const int*   ei    = (const int*)d_in[1];
    const float* ea    = (const float*)d_in[2];
    const int*   batch = (const int*)d_in[3];
    const float* w_init0 = (const float*)d_in[4];
    const float* w_root0 = (const float*)d_in[5];
    const float* b0      = (const float*)d_in[6];
    const float* w_init1 = (const float*)d_in[7];
    const float* w_root1 = (const float*)d_in[8];
    const float* b1      = (const float*)d_in[9];
    const float* mlp_w1  = (const float*)d_in[10];
    const float* mlp_b1  = (const float*)d_in[11];
    const float* mlp_w2  = (const float*)d_in[12];
    const float* mlp_b2  = (const float*)d_in[13];
    float* out = (float*)d_out;

    const int TB = 256;
    int nBlkE = (Ee + TB - 1) / TB;
    dim3 gg((Nn + 127) / 128, 2);

    cudaStream_t s2;
    cudaEvent_t evFork, evJoin;
    bool forked = (cudaStreamCreateWithFlags(&s2, cudaStreamNonBlocking) == cudaSuccess) &&
                  (cudaEventCreateWithFlags(&evFork, cudaEventDisableTiming) == cudaSuccess) &&
                  (cudaEventCreateWithFlags(&evJoin, cudaEventDisableTiming) == cudaSuccess);

    if (forked && cudaEventRecord(evFork, 0) == cudaSuccess &&
        cudaStreamWaitEvent(s2, evFork, 0) == cudaSuccess) {
        int nz = ((NG * HID > Nn ? NG * HID : Nn) + TB - 1) / TB;
        k_zero<<<nz, TB, 0, s2>>>();
        k_degcnt<<<nBlkE, TB, 0, s2>>>(ei, ea);
        k_scan1<<<NB_SCAN, 1024, 0, s2>>>();
        k_scan2<<<1, 128, 0, s2>>>();
        k_scan3<<<NB_SCAN, 1024, 0, s2>>>();
        k_scatter<<<nBlkE, TB, 0, s2>>>(ei, ea);
        cudaEventRecord(evJoin, s2);

        k_split_x<<<(Nn * 64 + TB - 1) / TB, TB>>>(x);
        k_wsplit<true><<<(256 * 256 + TB - 1) / TB, TB>>>(w_init0, w_root0);
        k_wsplit<false><<<(256 * 128 + TB - 1) / TB, TB>>>(w_init1, w_root1);
        k_mma<true><<<gg, 256>>>();

        cudaStreamWaitEvent(0, evJoin, 0);
    } else {
        int nz = ((NG * HID > Nn ? NG * HID : Nn) + TB - 1) / TB;
        k_zero<<<nz, TB>>>();
        k_degcnt<<<nBlkE, TB>>>(ei, ea);
        k_scan1<<<NB_SCAN, 1024>>>();
        k_scan2<<<1, 128>>>();
        k_scan3<<<NB_SCAN, 1024>>>();
        k_scatter<<<nBlkE, TB>>>(ei, ea);
        k_split_x<<<(Nn * 64 + TB - 1) / TB, TB>>>(x);
        k_wsplit<true><<<(256 * 256 + TB - 1) / TB, TB>>>(w_init0, w_root0);
        k_wsplit<false><<<(256 * 128 + TB - 1) / TB, TB>>>(w_init1, w_root1);
        k_mma<true><<<gg, 256>>>();
    }

    k_agg0<<<(Nn + 7) / 8, 256>>>(b0);
    k_mma<false><<<gg, 256>>>();
    k_agg1<<<(Nn + 7) / 8, 256>>>(b1, batch);
    k_mlp<<<NG, 256>>>(mlp_w1, mlp_b1, mlp_w2, mlp_b2, out);

    if (forked) {
        cudaStreamDestroy(s2);
        cudaEventDestroy(evFork);
        cudaEventDestroy(evJoin);
    }
}

// round 13
// speedup vs baseline: 3.1023x; 1.0231x over previous
#include <cuda_runtime.h>
#include <cuda_fp16.h>
#include <cstdint>

// Problem constants
#define Nn   100000
#define Ee   1600000
#define HID  128
#define NG   512
#define NB_SCAN 98        // ceil(100000/1024)

// ---------------- scratch (static device memory) -----------------------------
__device__ __align__(128) __half g_Hi[(size_t)Nn * 128];
__device__ __align__(128) __half g_Hr[(size_t)Nn * 128];
__device__ __align__(128) __half g_A0[(size_t)Nn * 256];
__device__ __align__(128) __half g_A1[(size_t)Nn * 128];
__device__ __align__(128) __half g_B0[256 * 256];
__device__ __align__(128) __half g_B1[256 * 128];
__device__ float g_deg[Nn];
__device__ int   g_cnt[Nn];
__device__ int   g_off[Nn];
__device__ int   g_cur[Nn];
__device__ int   g_src[Ee];
__device__ float g_nrm_s[Ee];
__device__ int   g_psum[NB_SCAN];
__device__ int   g_boff[NB_SCAN];
__device__ float g_pool[NG * HID];
__device__ float g_pcnt[NG];

// ---------------- PTX helpers (base sm_100 features only) --------------------
__device__ __forceinline__ uint32_t s2u(const void* p) {
    uint32_t a;
    asm("{ .reg .u64 t; cvta.to.shared.u64 t, %1; cvt.u32.u64 %0, t; }" : "=r"(a) : "l"(p));
    return a;
}
__device__ __forceinline__ void ldm_x4(uint32_t& r0, uint32_t& r1, uint32_t& r2, uint32_t& r3,
                                       uint32_t addr) {
    asm volatile("ldmatrix.sync.aligned.m8n8.x4.shared.b16 {%0,%1,%2,%3}, [%4];"
                 : "=r"(r0), "=r"(r1), "=r"(r2), "=r"(r3) : "r"(addr));
}
__device__ __forceinline__ void ldm_x2(uint32_t& r0, uint32_t& r1, uint32_t addr) {
    asm volatile("ldmatrix.sync.aligned.m8n8.x2.shared.b16 {%0,%1}, [%2];"
                 : "=r"(r0), "=r"(r1) : "r"(addr));
}
__device__ __forceinline__ void mma_f16(float* c, const uint32_t* a, const uint32_t* b) {
    asm volatile(
        "mma.sync.aligned.m16n8k16.row.col.f32.f16.f16.f32 "
        "{%0,%1,%2,%3}, {%4,%5,%6,%7}, {%8,%9}, {%0,%1,%2,%3};"
        : "+f"(c[0]), "+f"(c[1]), "+f"(c[2]), "+f"(c[3])
        : "r"(a[0]), "r"(a[1]), "r"(a[2]), "r"(a[3]), "r"(b[0]), "r"(b[1]));
}
__device__ __forceinline__ void cpa16(uint32_t saddr, const void* gaddr) {
    asm volatile("cp.async.cg.shared.global [%0], [%1], 16;" :: "r"(saddr), "l"(gaddr));
}
__device__ __forceinline__ void cpa_commit(void) {
    asm volatile("cp.async.commit_group;" ::: "memory");
}
template <int N>
__device__ __forceinline__ void cpa_wait(void) {
    asm volatile("cp.async.wait_group %0;" :: "n"(N) : "memory");
}

// ---------------- fused zero + CSR build kernels ------------------------------
__global__ void k_zero(void) {
    int i = blockIdx.x * blockDim.x + threadIdx.x;
    if (i < Nn) { g_deg[i] = 0.f; g_cnt[i] = 0; }
    if (i < NG * HID) g_pool[i] = 0.f;
    if (i < NG) g_pcnt[i] = 0.f;
}
__global__ void k_degcnt(const int* __restrict__ ei, const float* __restrict__ w) {
    int e = blockIdx.x * blockDim.x + threadIdx.x;
    if (e >= Ee) return;
    int col = ei[Ee + e];
    atomicAdd(&g_deg[col], w[e]);
    atomicAdd(&g_cnt[col], 1);
}
__global__ void k_scan1(void) {
    __shared__ int s[1024];
    int t = threadIdx.x;
    int i = blockIdx.x * 1024 + t;
    if (i < Nn) {
        float d = g_deg[i];
        g_deg[i] = (d > 0.f) ? rsqrtf(d) : 0.f;
    }
    s[t] = (i < Nn) ? g_cnt[i] : 0;
    __syncthreads();
    for (int d = 512; d > 0; d >>= 1) {
        if (t < d) s[t] += s[t + d];
        __syncthreads();
    }
    if (t == 0) g_psum[blockIdx.x] = s[0];
}
__global__ void k_scan2(void) {
    __shared__ int warpsum[4];
    int t = threadIdx.x;
    int lane = t & 31, w = t >> 5;
    int v = (t < NB_SCAN) ? g_psum[t] : 0;
    int inc = v;
    #pragma unroll
    for (int d = 1; d < 32; d <<= 1) {
        int o = __shfl_up_sync(0xFFFFFFFF, inc, d);
        if (lane >= d) inc += o;
    }
    if (lane == 31) warpsum[w] = inc;
    __syncthreads();
    int base = 0;
    #pragma unroll
    for (int k = 0; k < 4; k++) if (k < w) base += warpsum[k];
    if (t < NB_SCAN) g_boff[t] = base + inc - v;
}
__global__ void k_scan3(void) {
    __shared__ int s[1024];
    int t = threadIdx.x;
    int i = blockIdx.x * 1024 + t;
    int v = (i < Nn) ? g_cnt[i] : 0;
    s[t] = v;
    __syncthreads();
    for (int d = 1; d < 1024; d <<= 1) {
        int add = (t >= d) ? s[t - d] : 0;
        __syncthreads();
        s[t] += add;
        __syncthreads();
    }
    if (i < Nn) {
        int excl = g_boff[blockIdx.x] + s[t] - v;
        g_off[i] = excl;
        g_cur[i] = excl;
    }
}
__global__ void k_scatter(const int* __restrict__ ei, const float* __restrict__ w) {
    int e = blockIdx.x * blockDim.x + threadIdx.x;
    if (e >= Ee) return;
    int row = ei[e];
    int col = ei[Ee + e];
    int pos = atomicAdd(&g_cur[col], 1);
    g_src[pos] = row;
    g_nrm_s[pos] = g_deg[row] * w[e] * g_deg[col];
}

// ---------------- fp16 conversion preps --------------------------------------
__global__ void k_split_x(const float* __restrict__ x) {
    size_t i = (size_t)blockIdx.x * blockDim.x + threadIdx.x;
    if (i >= (size_t)Nn * 64) return;
    float4 v = ((const float4*)x)[i];
    __half2 a = __halves2half2(__float2half(v.x), __float2half(v.y));
    __half2 b = __halves2half2(__float2half(v.z), __float2half(v.w));
    ((__half2*)g_A0)[i * 2 + 0] = a;
    ((__half2*)g_A0)[i * 2 + 1] = b;
}
template <bool FIRST>
__global__ void k_wsplit(const float* __restrict__ wi, const float* __restrict__ wr) {
    const int K = FIRST ? 256 : 128;
    int idx = blockIdx.x * blockDim.x + threadIdx.x;
    if (idx >= 256 * K) return;
    int n = idx / K, k = idx % K;
    float w = (n < 128) ? wi[k * 128 + n] : wr[k * 128 + (n - 128)];
    if (FIRST) g_B0[idx] = __float2half(w);
    else       g_B1[idx] = __float2half(w);
}

// ---------------- pipelined mma.sync GEMM (BK=64, dynamic smem) --------------
#define SROW 72   // smem row stride in halves (64 data + 8 pad) -> 144 bytes
#define TILE_HALVES (128 * SROW)               // 9216 halves per tile
#define SMEM_BYTES (4 * TILE_HALVES * 2)       // 2 bufs x (A+B) = 73728 bytes
template <bool FIRST>
__global__ void __launch_bounds__(256, 2) k_mma(void) {
    constexpr int K  = FIRST ? 256 : 128;
    constexpr int NC = K / 64;
    extern __shared__ __align__(16) __half smem[];
    // layout: [buf0 A][buf0 B][buf1 A][buf1 B]
    __half* sA[2] = { smem,                   smem + 2 * TILE_HALVES };
    __half* sB[2] = { smem + TILE_HALVES,     smem + 3 * TILE_HALVES };

    const __half* Aw = FIRST ? g_A0 : g_A1;
    const __half* Bw = FIRST ? g_B0 : g_B1;

    int tid = threadIdx.x, lane = tid & 31, wid = tid >> 5;
    int warp_m = wid >> 2;
    int warp_n = wid & 3;
    int rowBase = blockIdx.x * 128;
    __half* Hout = (blockIdx.y == 0) ? g_Hi : g_Hr;
    int nBase = blockIdx.y * 128;

    // 2048 x 16B per chunk (A:1024, B:1024), 8 per thread
    auto issue_chunk = [&](int c, int buf) {
        int k0 = c * 64;
        #pragma unroll
        for (int j = tid; j < 2048; j += 256) {
            int isB = j >= 1024;
            int i = j & 1023;
            int row = i >> 3, q = i & 7;           // q: 8-half group within 64
            const __half* src;
            if (!isB) {
                int rg = rowBase + row;
                if (rg >= Nn) rg = Nn - 1;
                src = &Aw[(size_t)rg * K + k0 + q * 8];
            } else {
                src = &Bw[(size_t)(nBase + row) * K + k0 + q * 8];
            }
            uint32_t dst = s2u(&(isB ? sB : sA)[buf][row * SROW + q * 8]);
            cpa16(dst, src);
        }
        cpa_commit();
    };

    float acc[4][4][4] = {};

    issue_chunk(0, 0);
    for (int c = 0; c < NC; ++c) {
        int buf = c & 1;
        cpa_wait<0>();
        __syncthreads();
        if (c + 1 < NC) issue_chunk(c + 1, buf ^ 1);
        uint32_t aB = s2u(sA[buf]), bB = s2u(sB[buf]);
        #pragma unroll
        for (int kk = 0; kk < 4; kk++) {
            int k16 = kk * 16;
            uint32_t a[4][4];
            #pragma unroll
            for (int mt = 0; mt < 4; mt++) {
                int row = warp_m * 64 + mt * 16 + (lane & 15);
                uint32_t addr = aB + (uint32_t)(row * SROW + k16 + (lane >> 4) * 8) * 2;
                ldm_x4(a[mt][0], a[mt][1], a[mt][2], a[mt][3], addr);
            }
            uint32_t b[4][2];
            #pragma unroll
            for (int nt = 0; nt < 4; nt++) {
                int row = warp_n * 32 + nt * 8 + (lane & 7);
                uint32_t addr = bB + (uint32_t)(row * SROW + k16 + ((lane >> 3) & 1) * 8) * 2;
                ldm_x2(b[nt][0], b[nt][1], addr);
            }
            #pragma unroll
            for (int mt = 0; mt < 4; mt++)
                #pragma unroll
                for (int nt = 0; nt < 4; nt++)
                    mma_f16(acc[mt][nt], a[mt], b[nt]);
        }
        __syncthreads();
    }

    // epilogue: fp16 output (half2 stores)
    #pragma unroll
    for (int mt = 0; mt < 4; mt++) {
        int m0 = rowBase + warp_m * 64 + mt * 16 + (lane >> 2);
        int m1 = m0 + 8;
        #pragma unroll
        for (int nt = 0; nt < 4; nt++) {
            int col = warp_n * 32 + nt * 8 + (lane & 3) * 2;
            if (m0 < Nn) {
                *(__half2*)&Hout[(size_t)m0 * 128 + col] =
                    __halves2half2(__float2half(acc[mt][nt][0]), __float2half(acc[mt][nt][1]));
            }
            if (m1 < Nn) {
                *(__half2*)&Hout[(size_t)m1 * 128 + col] =
                    __halves2half2(__float2half(acc[mt][nt][2]), __float2half(acc[mt][nt][3]));
            }
        }
    }
}

// ---------------- Aggregation: warp per node, fp16 gathers -------------------
__device__ __forceinline__ void gather_add(float4& acc, const __half* rowp, float nm) {
    uint2 u = *(const uint2*)rowp;
    float2 f0 = __half22float2(*(__half2*)&u.x);
    float2 f1 = __half22float2(*(__half2*)&u.y);
    acc.x += nm * f0.x; acc.y += nm * f0.y;
    acc.z += nm * f1.x; acc.w += nm * f1.y;
}

__global__ void k_agg0(const float* __restrict__ bias) {
    int warp = threadIdx.x >> 5;
    int lane = threadIdx.x & 31;
    int n = blockIdx.x * 8 + warp;
    if (n >= Nn) return;
    int e = g_off[n];
    int end = e + g_cnt[n];
    float4 acc = make_float4(0.f, 0.f, 0.f, 0.f);
    for (; e + 1 < end; e += 2) {
        int s0 = g_src[e], s1 = g_src[e + 1];
        float n0 = g_nrm_s[e], n1 = g_nrm_s[e + 1];
        gather_add(acc, &g_Hi[(size_t)s0 * 128 + lane * 4], n0);
        gather_add(acc, &g_Hi[(size_t)s1 * 128 + lane * 4], n1);
    }
    if (e < end) {
        gather_add(acc, &g_Hi[(size_t)g_src[e] * 128 + lane * 4], g_nrm_s[e]);
    }
    float4 r;
    {
        uint2 u = *(const uint2*)&g_Hr[(size_t)n * 128 + lane * 4];
        float2 f0 = __half22float2(*(__half2*)&u.x);
        float2 f1 = __half22float2(*(__half2*)&u.y);
        r = make_float4(f0.x, f0.y, f1.x, f1.y);
    }
    float4 b = *(const float4*)&bias[lane * 4];
    float o0 = fmaxf(acc.x + r.x + b.x, 0.f);
    float o1 = fmaxf(acc.y + r.y + b.y, 0.f);
    float o2 = fmaxf(acc.z + r.z + b.z, 0.f);
    float o3 = fmaxf(acc.w + r.w + b.w, 0.f);
    __half2* ph = (__half2*)&g_A1[(size_t)n * 128 + lane * 4];
    ph[0] = __halves2half2(__float2half(o0), __float2half(o1));
    ph[1] = __halves2half2(__float2half(o2), __float2half(o3));
}

__global__ void k_agg1(const float* __restrict__ bias, const int* __restrict__ batch) {
    int warp = threadIdx.x >> 5;
    int lane = threadIdx.x & 31;
    int n = blockIdx.x * 8 + warp;
    if (n >= Nn) return;
    int e = g_off[n];
    int end = e + g_cnt[n];
    float4 acc = make_float4(0.f, 0.f, 0.f, 0.f);
    for (; e + 1 < end; e += 2) {
        int s0 = g_src[e], s1 = g_src[e + 1];
        float n0 = g_nrm_s[e], n1 = g_nrm_s[e + 1];
        gather_add(acc, &g_Hi[(size_t)s0 * 128 + lane * 4], n0);
        gather_add(acc, &g_Hi[(size_t)s1 * 128 + lane * 4], n1);
    }
    if (e < end) {
        gather_add(acc, &g_Hi[(size_t)g_src[e] * 128 + lane * 4], g_nrm_s[e]);
    }
    float4 r;
    {
        uint2 u = *(const uint2*)&g_Hr[(size_t)n * 128 + lane * 4];
        float2 f0 = __half22float2(*(__half2*)&u.x);
        float2 f1 = __half22float2(*(__half2*)&u.y);
        r = make_float4(f0.x, f0.y, f1.x, f1.y);
    }
    float4 b = *(const float4*)&bias[lane * 4];
    float4 o;
    o.x = fmaxf(acc.x + r.x + b.x, 0.f);
    o.y = fmaxf(acc.y + r.y + b.y, 0.f);
    o.z = fmaxf(acc.z + r.z + b.z, 0.f);
    o.w = fmaxf(acc.w + r.w + b.w, 0.f);
    int g = batch[n];
    float* p = &g_pool[(size_t)g * 128 + lane * 4];
    atomicAdd(p + 0, o.x);
    atomicAdd(p + 1, o.y);
    atomicAdd(p + 2, o.z);
    atomicAdd(p + 3, o.w);
    if (lane == 0) atomicAdd(&g_pcnt[g], 1.f);
}

// ---------------- pool finalize + MLP ----------------------------------------
__global__ void k_mlp(const float* __restrict__ w1, const float* __restrict__ b1,
                      const float* __restrict__ w2, const float* __restrict__ b2,
                      float* __restrict__ out) {
    __shared__ float gx[128];
    __shared__ float hid[256];
    int g = blockIdx.x;
    int t = threadIdx.x;
    if (t < 128) {
        float c = fmaxf(g_pcnt[g], 1.f);
        gx[t] = g_pool[(size_t)g * 128 + t] / c;
    }
    __syncthreads();
    float acc = b1[t];
    #pragma unroll 8
    for (int k = 0; k < 128; k++) acc += gx[k] * w1[k * 256 + t];
    hid[t] = fmaxf(acc, 0.f);
    __syncthreads();
    int warp = t >> 5, lane = t & 31;
    if (warp < 2) {
        int c = warp;
        float s = 0.f;
        for (int k = lane; k < 256; k += 32) s += hid[k] * w2[k * 2 + c];
        #pragma unroll
        for (int d = 16; d > 0; d >>= 1) s += __shfl_xor_sync(0xFFFFFFFF, s, d);
        if (lane == 0) out[g * 2 + c] = s + b2[c];
    }
}

// ---------------- launch (fork-join: CSR build overlaps split+GEMM0) ----------
extern "C" void kernel_launch(void* const* d_in, const int* in_sizes, int n_in,
                              void* d_out, int out_size) {
    const float* x     = (const float*)d_in[0];
    const int*   ei    = (const int*)d_in[1];
    const float* ea    = (const float*)d_in[2];
    const int*   batch = (const int*)d_in[3];
    const float* w_init0 = (const float*)d_in[4];
    const float* w_root0 = (const float*)d_in[5];
    const float* b0      = (const float*)d_in[6];
    const float* w_init1 = (const float*)d_in[7];
    const float* w_root1 = (const float*)d_in[8];
    const float* b1      = (const float*)d_in[9];
    const float* mlp_w1  = (const float*)d_in[10];
    const float* mlp_b1  = (const float*)d_in[11];
    const float* mlp_w2  = (const float*)d_in[12];
    const float* mlp_b2  = (const float*)d_in[13];
    float* out = (float*)d_out;

    // raise dynamic smem limit for the GEMM kernels (idempotent, capture-safe)
    cudaFuncSetAttribute(k_mma<true>,  cudaFuncAttributeMaxDynamicSharedMemorySize, SMEM_BYTES);
    cudaFuncSetAttribute(k_mma<false>, cudaFuncAttributeMaxDynamicSharedMemorySize, SMEM_BYTES);

    const int TB = 256;
    int nBlkE = (Ee + TB - 1) / TB;
    dim3 gg((Nn + 127) / 128, 2);

    cudaStream_t s2;
    cudaEvent_t evFork, evJoin;
    bool forked = (cudaStreamCreateWithFlags(&s2, cudaStreamNonBlocking) == cudaSuccess) &&
                  (cudaEventCreateWithFlags(&evFork, cudaEventDisableTiming) == cudaSuccess) &&
                  (cudaEventCreateWithFlags(&evJoin, cudaEventDisableTiming) == cudaSuccess);

    if (forked && cudaEventRecord(evFork, 0) == cudaSuccess &&
        cudaStreamWaitEvent(s2, evFork, 0) == cudaSuccess) {
        int nz = ((NG * HID > Nn ? NG * HID : Nn) + TB - 1) / TB;
        k_zero<<<nz, TB, 0, s2>>>();
        k_degcnt<<<nBlkE, TB, 0, s2>>>(ei, ea);
        k_scan1<<<NB_SCAN, 1024, 0, s2>>>();
        k_scan2<<<1, 128, 0, s2>>>();
        k_scan3<<<NB_SCAN, 1024, 0, s2>>>();
        k_scatter<<<nBlkE, TB, 0, s2>>>(ei, ea);
        cudaEventRecord(evJoin, s2);

        k_split_x<<<(Nn * 64 + TB - 1) / TB, TB>>>(x);
        k_wsplit<true><<<(256 * 256 + TB - 1) / TB, TB>>>(w_init0, w_root0);
        k_wsplit<false><<<(256 * 128 + TB - 1) / TB, TB>>>(w_init1, w_root1);
        k_mma<true><<<gg, 256, SMEM_BYTES>>>();

        cudaStreamWaitEvent(0, evJoin, 0);
    } else {
        int nz = ((NG * HID > Nn ? NG * HID : Nn) + TB - 1) / TB;
        k_zero<<<nz, TB>>>();
        k_degcnt<<<nBlkE, TB>>>(ei, ea);
        k_scan1<<<NB_SCAN, 1024>>>();
        k_scan2<<<1, 128>>>();
        k_scan3<<<NB_SCAN, 1024>>>();
        k_scatter<<<nBlkE, TB>>>(ei, ea);
        k_split_x<<<(Nn * 64 + TB - 1) / TB, TB>>>(x);
        k_wsplit<true><<<(256 * 256 + TB - 1) / TB, TB>>>(w_init0, w_root0);
        k_wsplit<false><<<(256 * 128 + TB - 1) / TB, TB>>>(w_init1, w_root1);
        k_mma<true><<<gg, 256, SMEM_BYTES>>>();
    }

    k_agg0<<<(Nn + 7) / 8, 256>>>(b0);
    k_mma<false><<<gg, 256, SMEM_BYTES>>>();
    k_agg1<<<(Nn + 7) / 8, 256>>>(b1, batch);
    k_mlp<<<NG, 256>>>(mlp_w1, mlp_b1, mlp_w2, mlp_b2, out);

    if (forked) {
        cudaStreamDestroy(s2);
        cudaEventDestroy(evFork);
        cudaEventDestroy(evJoin);
    }
}